// round 1
// baseline (speedup 1.0000x reference)
#include <cuda_runtime.h>
#include <math.h>

// Problem constants
#define BB 64
#define SS 256
#define HH 1024
#define MM (BB*SS)          // 16384
#define H4 (4*HH)           // 4096
#define H3 (3*HH)           // 3072
#define NCTA_SCAN 128

// ---------------- scratch (device globals; no cudaMalloc allowed) ----------
__device__ float g_z[(size_t)MM * H4];      // 256 MB
__device__ float g_h1[(size_t)MM * HH];     // 64 MB
__device__ float g_Dr[(size_t)MM * HH];     // 64 MB
__device__ float g_Dw[(size_t)MM * HH];     // 64 MB
__device__ float g_Zs[MM];
__device__ float g_G[MM];
__device__ float g_UrT[HH * HH];
__device__ float g_UT[HH * HH];
__device__ float g_hping[BB * HH];
__device__ float g_hpong[BB * HH];
__device__ unsigned g_bar_count;
__device__ unsigned g_bar_gen;

// ---------------- build z = [D*Q, D*P, |D-Q|, |D-P|] -----------------------
__global__ void build_z_kernel(const float* __restrict__ D,
                               const float* __restrict__ Q,
                               const float* __restrict__ P) {
    int idx = blockIdx.x * blockDim.x + threadIdx.x;   // one float4 of D
    if (idx >= MM * (HH/4)) return;
    int k4 = idx & 255;          // H/4 = 256
    int m  = idx >> 8;
    int b  = m >> 8;             // S = 256
    float4 d = ((const float4*)D)[idx];
    float4 q = ((const float4*)Q)[(b << 8) + k4];
    float4 p = ((const float4*)P)[(b << 8) + k4];
    float4* zrow = (float4*)(g_z + (size_t)m * H4);
    zrow[k4]       = make_float4(d.x*q.x, d.y*q.y, d.z*q.z, d.w*q.w);
    zrow[256 + k4] = make_float4(d.x*p.x, d.y*p.y, d.z*p.z, d.w*p.w);
    zrow[512 + k4] = make_float4(fabsf(d.x-q.x), fabsf(d.y-q.y), fabsf(d.z-q.z), fabsf(d.w-q.w));
    zrow[768 + k4] = make_float4(fabsf(d.x-p.x), fabsf(d.y-p.y), fabsf(d.z-p.z), fabsf(d.w-p.w));
}

// ---------------- 128x128x8 SGEMM, C = act(A@B + bias) ---------------------
// A: MxK row-major, B: KxN row-major. M%128==0, N%128==0, K%8==0.
__global__ __launch_bounds__(256) void sgemm128(const float* __restrict__ A,
                                                const float* __restrict__ Bw,
                                                const float* __restrict__ bias,
                                                float* __restrict__ C,
                                                int M, int N, int K, int act) {
    __shared__ float As[8][128];
    __shared__ float Bs[8][128];
    const int bm = blockIdx.y * 128;
    const int bn = blockIdx.x * 128;
    const int tid = threadIdx.x;
    const int tr = tid >> 4;          // 0..15
    const int tc = tid & 15;          // 0..15
    const int a_row  = tid >> 1;      // 0..127
    const int a_col4 = (tid & 1) * 4; // 0 or 4
    const int b_row  = tid >> 5;      // 0..7
    const int b_col4 = (tid & 31) * 4;

    float acc[8][8];
#pragma unroll
    for (int i = 0; i < 8; ++i)
#pragma unroll
        for (int j = 0; j < 8; ++j) acc[i][j] = 0.f;

    for (int k0 = 0; k0 < K; k0 += 8) {
        float4 av = *(const float4*)(A + (size_t)(bm + a_row) * K + k0 + a_col4);
        float4 bv = *(const float4*)(Bw + (size_t)(k0 + b_row) * N + bn + b_col4);
        As[a_col4 + 0][a_row] = av.x;
        As[a_col4 + 1][a_row] = av.y;
        As[a_col4 + 2][a_row] = av.z;
        As[a_col4 + 3][a_row] = av.w;
        *(float4*)&Bs[b_row][b_col4] = bv;
        __syncthreads();
#pragma unroll
        for (int kk = 0; kk < 8; ++kk) {
            float4 a0 = *(const float4*)&As[kk][tr * 8];
            float4 a1 = *(const float4*)&As[kk][tr * 8 + 4];
            float4 b0 = *(const float4*)&Bs[kk][tc * 8];
            float4 b1 = *(const float4*)&Bs[kk][tc * 8 + 4];
            float ar[8] = {a0.x,a0.y,a0.z,a0.w,a1.x,a1.y,a1.z,a1.w};
            float br[8] = {b0.x,b0.y,b0.z,b0.w,b1.x,b1.y,b1.z,b1.w};
#pragma unroll
            for (int i = 0; i < 8; ++i)
#pragma unroll
                for (int j = 0; j < 8; ++j) acc[i][j] += ar[i] * br[j];
        }
        __syncthreads();
    }

    // epilogue
    float bv0[8];
#pragma unroll
    for (int j = 0; j < 8; ++j) bv0[j] = bias[bn + tc * 8 + j];
#pragma unroll
    for (int i = 0; i < 8; ++i) {
        float out[8];
#pragma unroll
        for (int j = 0; j < 8; ++j) {
            float v = acc[i][j] + bv0[j];
            out[j] = act ? tanhf(v) : v;
        }
        float* Crow = C + (size_t)(bm + tr * 8 + i) * N + bn + tc * 8;
        *(float4*)Crow       = make_float4(out[0], out[1], out[2], out[3]);
        *(float4*)(Crow + 4) = make_float4(out[4], out[5], out[6], out[7]);
    }
}

// ---------------- Zs = h1 @ W2 + b2 (GEMV) ----------------------------------
__global__ void zs_gemv_kernel(const float* __restrict__ W2,
                               const float* __restrict__ b2) {
    int m = blockIdx.x;
    int tid = threadIdx.x;  // 128
    const float4* hr = (const float4*)(g_h1 + (size_t)m * HH);
    const float4* w  = (const float4*)W2;
    float s = 0.f;
#pragma unroll
    for (int k = tid; k < 256; k += 128) {
        float4 a = hr[k], bb = w[k];
        s += a.x*bb.x + a.y*bb.y + a.z*bb.z + a.w*bb.w;
    }
#pragma unroll
    for (int off = 16; off; off >>= 1) s += __shfl_down_sync(0xffffffffu, s, off);
    __shared__ float ws[4];
    if ((tid & 31) == 0) ws[tid >> 5] = s;
    __syncthreads();
    if (tid == 0) g_Zs[m] = ws[0] + ws[1] + ws[2] + ws[3] + b2[0];
}

// ---------------- softmax over S per batch ----------------------------------
__global__ void softmax_kernel() {
    int b = blockIdx.x;
    int tid = threadIdx.x; // 256 == S
    __shared__ float red[256];
    float v = g_Zs[b * SS + tid];
    red[tid] = v; __syncthreads();
#pragma unroll
    for (int off = 128; off; off >>= 1) {
        if (tid < off) red[tid] = fmaxf(red[tid], red[tid + off]);
        __syncthreads();
    }
    float mx = red[0]; __syncthreads();
    float e = expf(v - mx);
    red[tid] = e; __syncthreads();
#pragma unroll
    for (int off = 128; off; off >>= 1) {
        if (tid < off) red[tid] += red[tid + off];
        __syncthreads();
    }
    g_G[b * SS + tid] = e / red[0];
}

// ---------------- HxH transpose --------------------------------------------
__global__ void transpose_kernel(const float* __restrict__ src, float* __restrict__ dst) {
    __shared__ float tile[32][33];
    int x = blockIdx.x * 32 + threadIdx.x;
    int y = blockIdx.y * 32 + threadIdx.y;
#pragma unroll
    for (int i = 0; i < 4; ++i)
        tile[threadIdx.y + i * 8][threadIdx.x] = src[(size_t)(y + i * 8) * HH + x];
    __syncthreads();
    x = blockIdx.y * 32 + threadIdx.x;
    y = blockIdx.x * 32 + threadIdx.y;
#pragma unroll
    for (int i = 0; i < 4; ++i)
        dst[(size_t)(y + i * 8) * HH + x] = tile[threadIdx.x][threadIdx.y + i * 8];
}

// ---------------- init (zero h0, reset barrier) ------------------------------
__global__ void init_kernel() {
    int i = blockIdx.x * blockDim.x + threadIdx.x;
    if (i < BB * HH) g_hping[i] = 0.f;
    if (i == 0) { g_bar_count = 0u; g_bar_gen = 0u; }
}

// ---------------- grid barrier ----------------------------------------------
__device__ __forceinline__ void grid_sync(unsigned target) {
    __syncthreads();
    if (threadIdx.x == 0) {
        __threadfence();
        unsigned prev = atomicAdd(&g_bar_count, 1u);
        if (prev == NCTA_SCAN - 1) {
            g_bar_count = 0u;
            __threadfence();
            atomicExch(&g_bar_gen, target);
        } else {
            while (*((volatile unsigned*)&g_bar_gen) < target) { __nanosleep(64); }
        }
        __threadfence();
    }
    __syncthreads();
}

// ---------------- persistent scan kernel ------------------------------------
// 128 CTAs x 128 threads. CTA owns 8 output columns j; weights resident in smem.
__global__ __launch_bounds__(128) void scan_kernel(const float* __restrict__ bur,
                                                   const float* __restrict__ bu,
                                                   float* __restrict__ hs_out) {
    extern __shared__ float sm[];
    float* wr_s = sm;                 // [8][1028]
    float* wu_s = sm + 8 * 1028;      // [8][1028]
    float* sh   = sm + 16 * 1028;     // [64][68]
    const int tid = threadIdx.x;
    const int jl  = tid & 7;          // 0..7
    const int bg  = tid >> 3;         // 0..15
    const int j   = blockIdx.x * 8 + jl;

    // preload weight slices (transposed: row j contiguous over k)
    for (int idx = tid; idx < 2048; idx += 128) {       // 2048 float4s
        int jj = idx >> 8;
        int k4 = idx & 255;
        float4 w1 = *(const float4*)(g_UrT + (size_t)(blockIdx.x * 8 + jj) * HH + k4 * 4);
        float4 w2 = *(const float4*)(g_UT  + (size_t)(blockIdx.x * 8 + jj) * HH + k4 * 4);
        *(float4*)&wr_s[jj * 1028 + k4 * 4] = w1;
        *(float4*)&wu_s[jj * 1028 + k4 * 4] = w2;
    }
    const float burj = bur[j];
    const float buj  = bu[j];
    __syncthreads();

    const int r0 = tid >> 4;          // 0..7  (h-tile load row base)
    const int c4 = (tid & 15) * 4;    // 0..60

    for (int t = 0; t < SS; ++t) {
        const float* hcur = (t & 1) ? g_hpong : g_hping;
        float*       hnxt = (t & 1) ? g_hping : g_hpong;
        float accR[4] = {0.f, 0.f, 0.f, 0.f};
        float accU[4] = {0.f, 0.f, 0.f, 0.f};

        for (int kc = 0; kc < HH; kc += 64) {
            // cooperative load of h[0:64][kc:kc+64] (bypass L1: cross-CTA data)
#pragma unroll
            for (int r = 0; r < 8; ++r) {
                float4 hv = __ldcg((const float4*)(hcur + (size_t)(r0 + r * 8) * HH + kc + c4));
                *(float4*)&sh[(r0 + r * 8) * 68 + c4] = hv;
            }
            __syncthreads();
#pragma unroll
            for (int k = 0; k < 64; k += 4) {
                float4 wr4 = *(const float4*)&wr_s[jl * 1028 + kc + k];
                float4 wu4 = *(const float4*)&wu_s[jl * 1028 + kc + k];
#pragma unroll
                for (int i = 0; i < 4; ++i) {
                    float4 h4 = *(const float4*)&sh[(bg * 4 + i) * 68 + k];
                    accR[i] += h4.x*wr4.x + h4.y*wr4.y + h4.z*wr4.z + h4.w*wr4.w;
                    accU[i] += h4.x*wu4.x + h4.y*wu4.y + h4.z*wu4.z + h4.w*wu4.w;
                }
            }
            __syncthreads();
        }

        // update h for this CTA's 4 b's x 1 j per thread
#pragma unroll
        for (int i = 0; i < 4; ++i) {
            int b = bg * 4 + i;
            size_t base = ((size_t)b * SS + t) * HH + j;
            float dr   = g_Dr[base];
            float dw   = g_Dw[base];
            float g    = g_G[b * SS + t];
            float hold = __ldcg(hcur + b * HH + j);
            float r  = 1.f / (1.f + expf(-(dr + accR[i] + burj)));
            float ht = tanhf(dw + r * (accU[i] + buj));
            float hnew = g * ht + (1.f - g) * hold;
            hnxt[b * HH + j] = hnew;
            hs_out[base] = hnew;
        }
        grid_sync((unsigned)(t + 1));
    }
}

// ---------------- final next_mem = relu([P, C, Q] @ Wm + bm) -----------------
__global__ void next_mem_kernel(const float* __restrict__ P,
                                const float* __restrict__ Q,
                                const float* __restrict__ Wm,
                                const float* __restrict__ bm,
                                float* __restrict__ out) {
    __shared__ float srow[H3];
    int b = blockIdx.x;
    int tid = threadIdx.x;  // 256
    for (int i = tid; i < HH; i += 256) {
        srow[i]            = P[b * HH + i];
        srow[HH + i]       = g_hping[b * HH + i];   // final h (S even -> ping)
        srow[2 * HH + i]   = Q[b * HH + i];
    }
    __syncthreads();
    float acc0 = bm[tid], acc1 = bm[tid + 256], acc2 = bm[tid + 512], acc3 = bm[tid + 768];
    for (int k = 0; k < H3; ++k) {
        float s = srow[k];
        const float* w = Wm + (size_t)k * HH + tid;
        acc0 += s * w[0];
        acc1 += s * w[256];
        acc2 += s * w[512];
        acc3 += s * w[768];
    }
    out[b * HH + tid]       = fmaxf(acc0, 0.f);
    out[b * HH + tid + 256] = fmaxf(acc1, 0.f);
    out[b * HH + tid + 512] = fmaxf(acc2, 0.f);
    out[b * HH + tid + 768] = fmaxf(acc3, 0.f);
}

// ---------------- launch ----------------------------------------------------
extern "C" void kernel_launch(void* const* d_in, const int* in_sizes, int n_in,
                              void* d_out, int out_size) {
    const float* D   = (const float*)d_in[0];
    const float* Q   = (const float*)d_in[1];
    const float* P   = (const float*)d_in[2];   // prev_mem
    const float* Wr  = (const float*)d_in[3];
    const float* br  = (const float*)d_in[4];
    const float* Ur  = (const float*)d_in[5];
    const float* bur = (const float*)d_in[6];
    const float* Wx  = (const float*)d_in[7];
    const float* bx  = (const float*)d_in[8];
    const float* U   = (const float*)d_in[9];
    const float* bu  = (const float*)d_in[10];
    const float* W1  = (const float*)d_in[11];
    const float* b1  = (const float*)d_in[12];
    const float* W2  = (const float*)d_in[13];
    const float* b2  = (const float*)d_in[14];
    const float* Wm  = (const float*)d_in[15];
    const float* bm  = (const float*)d_in[16];

    float* out_next = (float*)d_out;            // (B,1,H)
    float* out_hs   = (float*)d_out + BB * HH;  // (B,S,H)

    static int smem_set = 0;
    const int scan_smem = (16 * 1028 + 64 * 68) * 4;   // 83,200 B
    if (!smem_set) {
        cudaFuncSetAttribute(scan_kernel, cudaFuncAttributeMaxDynamicSharedMemorySize, scan_smem);
        smem_set = 1;
    }

    float *gz, *gh1, *gDr, *gDw, *gUrT, *gUT;
    cudaGetSymbolAddress((void**)&gz, g_z);
    cudaGetSymbolAddress((void**)&gh1, g_h1);
    cudaGetSymbolAddress((void**)&gDr, g_Dr);
    cudaGetSymbolAddress((void**)&gDw, g_Dw);
    cudaGetSymbolAddress((void**)&gUrT, g_UrT);
    cudaGetSymbolAddress((void**)&gUT, g_UT);

    // 1) z features
    build_z_kernel<<<MM * (HH/4) / 256, 256>>>(D, Q, P);
    // 2) h1 = tanh(z @ W1 + b1)
    sgemm128<<<dim3(HH/128, MM/128), 256>>>(gz, W1, b1, gh1, MM, HH, H4, 1);
    // 3) Zs = h1 @ W2 + b2 ; 4) softmax -> G
    zs_gemv_kernel<<<MM, 128>>>(W2, b2);
    softmax_kernel<<<BB, 256>>>();
    // 5) Dr, Dw
    sgemm128<<<dim3(HH/128, MM/128), 256>>>(D, Wr, br, gDr, MM, HH, HH, 0);
    sgemm128<<<dim3(HH/128, MM/128), 256>>>(D, Wx, bx, gDw, MM, HH, HH, 0);
    // 6) transpose recurrent weights for coalesced scan access
    transpose_kernel<<<dim3(32, 32), dim3(32, 8)>>>(Ur, gUrT);
    transpose_kernel<<<dim3(32, 32), dim3(32, 8)>>>(U, gUT);
    // 7) init h0 + barrier state
    init_kernel<<<256, 256>>>();
    // 8) sequential scan (persistent, 1 grid barrier per step)
    scan_kernel<<<NCTA_SCAN, 128, scan_smem>>>(bur, bu, out_hs);
    // 9) next_mem
    next_mem_kernel<<<BB, 256>>>(P, Q, Wm, bm, out_next);
}

// round 2
// speedup vs baseline: 1.0008x; 1.0008x over previous
#include <cuda_runtime.h>
#include <math.h>

// Problem constants
#define BB 64
#define SS 256
#define HH 1024
#define MM (BB*SS)          // 16384
#define H4 (4*HH)           // 4096
#define H3 (3*HH)           // 3072
#define NCTA_SCAN 128

// ---------------- scratch (device globals; no cudaMalloc allowed) ----------
__device__ float g_z[(size_t)MM * H4];      // 256 MB
__device__ float g_h1[(size_t)MM * HH];     // 64 MB
__device__ float g_Dr[(size_t)MM * HH];     // 64 MB
__device__ float g_Dw[(size_t)MM * HH];     // 64 MB
__device__ float g_Zs[MM];
__device__ float g_G[MM];
__device__ float g_UrT[HH * HH];
__device__ float g_UT[HH * HH];
__device__ float g_hping[BB * HH];
__device__ float g_hpong[BB * HH];
__device__ unsigned g_bar_count;
__device__ unsigned g_bar_gen;

// ---------------- build z = [D*Q, D*P, |D-Q|, |D-P|] -----------------------
__global__ void build_z_kernel(const float* __restrict__ D,
                               const float* __restrict__ Q,
                               const float* __restrict__ P) {
    int idx = blockIdx.x * blockDim.x + threadIdx.x;   // one float4 of D
    if (idx >= MM * (HH/4)) return;
    int k4 = idx & 255;          // H/4 = 256
    int m  = idx >> 8;
    int b  = m >> 8;             // S = 256
    float4 d = ((const float4*)D)[idx];
    float4 q = ((const float4*)Q)[(b << 8) + k4];
    float4 p = ((const float4*)P)[(b << 8) + k4];
    float4* zrow = (float4*)(g_z + (size_t)m * H4);
    zrow[k4]       = make_float4(d.x*q.x, d.y*q.y, d.z*q.z, d.w*q.w);
    zrow[256 + k4] = make_float4(d.x*p.x, d.y*p.y, d.z*p.z, d.w*p.w);
    zrow[512 + k4] = make_float4(fabsf(d.x-q.x), fabsf(d.y-q.y), fabsf(d.z-q.z), fabsf(d.w-q.w));
    zrow[768 + k4] = make_float4(fabsf(d.x-p.x), fabsf(d.y-p.y), fabsf(d.z-p.z), fabsf(d.w-p.w));
}

// ---------------- 128x128x8 SGEMM, C = act(A@B + bias) ---------------------
// A: MxK row-major, B: KxN row-major. M%128==0, N%128==0, K%8==0.
__global__ __launch_bounds__(256) void sgemm128(const float* __restrict__ A,
                                                const float* __restrict__ Bw,
                                                const float* __restrict__ bias,
                                                float* __restrict__ C,
                                                int M, int N, int K, int act) {
    __shared__ float As[8][128];
    __shared__ float Bs[8][128];
    const int bm = blockIdx.y * 128;
    const int bn = blockIdx.x * 128;
    const int tid = threadIdx.x;
    const int tr = tid >> 4;          // 0..15
    const int tc = tid & 15;          // 0..15
    const int a_row  = tid >> 1;      // 0..127
    const int a_col4 = (tid & 1) * 4; // 0 or 4
    const int b_row  = tid >> 5;      // 0..7
    const int b_col4 = (tid & 31) * 4;

    float acc[8][8];
#pragma unroll
    for (int i = 0; i < 8; ++i)
#pragma unroll
        for (int j = 0; j < 8; ++j) acc[i][j] = 0.f;

    for (int k0 = 0; k0 < K; k0 += 8) {
        float4 av = *(const float4*)(A + (size_t)(bm + a_row) * K + k0 + a_col4);
        float4 bv = *(const float4*)(Bw + (size_t)(k0 + b_row) * N + bn + b_col4);
        As[a_col4 + 0][a_row] = av.x;
        As[a_col4 + 1][a_row] = av.y;
        As[a_col4 + 2][a_row] = av.z;
        As[a_col4 + 3][a_row] = av.w;
        *(float4*)&Bs[b_row][b_col4] = bv;
        __syncthreads();
#pragma unroll
        for (int kk = 0; kk < 8; ++kk) {
            float4 a0 = *(const float4*)&As[kk][tr * 8];
            float4 a1 = *(const float4*)&As[kk][tr * 8 + 4];
            float4 b0 = *(const float4*)&Bs[kk][tc * 8];
            float4 b1 = *(const float4*)&Bs[kk][tc * 8 + 4];
            float ar[8] = {a0.x,a0.y,a0.z,a0.w,a1.x,a1.y,a1.z,a1.w};
            float br[8] = {b0.x,b0.y,b0.z,b0.w,b1.x,b1.y,b1.z,b1.w};
#pragma unroll
            for (int i = 0; i < 8; ++i)
#pragma unroll
                for (int j = 0; j < 8; ++j) acc[i][j] += ar[i] * br[j];
        }
        __syncthreads();
    }

    // epilogue
    float bv0[8];
#pragma unroll
    for (int j = 0; j < 8; ++j) bv0[j] = bias[bn + tc * 8 + j];
#pragma unroll
    for (int i = 0; i < 8; ++i) {
        float out[8];
#pragma unroll
        for (int j = 0; j < 8; ++j) {
            float v = acc[i][j] + bv0[j];
            out[j] = act ? tanhf(v) : v;
        }
        float* Crow = C + (size_t)(bm + tr * 8 + i) * N + bn + tc * 8;
        *(float4*)Crow       = make_float4(out[0], out[1], out[2], out[3]);
        *(float4*)(Crow + 4) = make_float4(out[4], out[5], out[6], out[7]);
    }
}

// ---------------- Zs = h1 @ W2 + b2 (GEMV) ----------------------------------
__global__ void zs_gemv_kernel(const float* __restrict__ W2,
                               const float* __restrict__ b2) {
    int m = blockIdx.x;
    int tid = threadIdx.x;  // 128
    const float4* hr = (const float4*)(g_h1 + (size_t)m * HH);
    const float4* w  = (const float4*)W2;
    float s = 0.f;
#pragma unroll
    for (int k = tid; k < 256; k += 128) {
        float4 a = hr[k], bb = w[k];
        s += a.x*bb.x + a.y*bb.y + a.z*bb.z + a.w*bb.w;
    }
#pragma unroll
    for (int off = 16; off; off >>= 1) s += __shfl_down_sync(0xffffffffu, s, off);
    __shared__ float ws[4];
    if ((tid & 31) == 0) ws[tid >> 5] = s;
    __syncthreads();
    if (tid == 0) g_Zs[m] = ws[0] + ws[1] + ws[2] + ws[3] + b2[0];
}

// ---------------- softmax over S per batch ----------------------------------
__global__ void softmax_kernel() {
    int b = blockIdx.x;
    int tid = threadIdx.x; // 256 == S
    __shared__ float red[256];
    float v = g_Zs[b * SS + tid];
    red[tid] = v; __syncthreads();
#pragma unroll
    for (int off = 128; off; off >>= 1) {
        if (tid < off) red[tid] = fmaxf(red[tid], red[tid + off]);
        __syncthreads();
    }
    float mx = red[0]; __syncthreads();
    float e = expf(v - mx);
    red[tid] = e; __syncthreads();
#pragma unroll
    for (int off = 128; off; off >>= 1) {
        if (tid < off) red[tid] += red[tid + off];
        __syncthreads();
    }
    g_G[b * SS + tid] = e / red[0];
}

// ---------------- HxH transpose --------------------------------------------
__global__ void transpose_kernel(const float* __restrict__ src, float* __restrict__ dst) {
    __shared__ float tile[32][33];
    int x = blockIdx.x * 32 + threadIdx.x;
    int y = blockIdx.y * 32 + threadIdx.y;
#pragma unroll
    for (int i = 0; i < 4; ++i)
        tile[threadIdx.y + i * 8][threadIdx.x] = src[(size_t)(y + i * 8) * HH + x];
    __syncthreads();
    x = blockIdx.y * 32 + threadIdx.x;
    y = blockIdx.x * 32 + threadIdx.y;
#pragma unroll
    for (int i = 0; i < 4; ++i)
        dst[(size_t)(y + i * 8) * HH + x] = tile[threadIdx.x][threadIdx.y + i * 8];
}

// ---------------- init (zero h0, reset barrier) ------------------------------
__global__ void init_kernel() {
    int i = blockIdx.x * blockDim.x + threadIdx.x;
    if (i < BB * HH) g_hping[i] = 0.f;
    if (i == 0) { g_bar_count = 0u; g_bar_gen = 0u; }
}

// ---------------- grid barrier ----------------------------------------------
__device__ __forceinline__ void grid_sync(unsigned target) {
    __syncthreads();
    if (threadIdx.x == 0) {
        __threadfence();
        unsigned prev = atomicAdd(&g_bar_count, 1u);
        if (prev == NCTA_SCAN - 1) {
            g_bar_count = 0u;
            __threadfence();
            atomicExch(&g_bar_gen, target);
        } else {
            while (*((volatile unsigned*)&g_bar_gen) < target) { __nanosleep(64); }
        }
        __threadfence();
    }
    __syncthreads();
}

// ---------------- persistent scan kernel ------------------------------------
// 128 CTAs x 128 threads. CTA owns 8 output columns j; weights resident in smem.
__global__ __launch_bounds__(128) void scan_kernel(const float* __restrict__ bur,
                                                   const float* __restrict__ bu,
                                                   float* __restrict__ hs_out) {
    extern __shared__ float sm[];
    float* wr_s = sm;                 // [8][1028]
    float* wu_s = sm + 8 * 1028;      // [8][1028]
    float* sh   = sm + 16 * 1028;     // [64][68]
    const int tid = threadIdx.x;
    const int jl  = tid & 7;          // 0..7
    const int bg  = tid >> 3;         // 0..15
    const int j   = blockIdx.x * 8 + jl;

    // preload weight slices (transposed: row j contiguous over k)
    for (int idx = tid; idx < 2048; idx += 128) {       // 2048 float4s
        int jj = idx >> 8;
        int k4 = idx & 255;
        float4 w1 = *(const float4*)(g_UrT + (size_t)(blockIdx.x * 8 + jj) * HH + k4 * 4);
        float4 w2 = *(const float4*)(g_UT  + (size_t)(blockIdx.x * 8 + jj) * HH + k4 * 4);
        *(float4*)&wr_s[jj * 1028 + k4 * 4] = w1;
        *(float4*)&wu_s[jj * 1028 + k4 * 4] = w2;
    }
    const float burj = bur[j];
    const float buj  = bu[j];
    __syncthreads();

    const int r0 = tid >> 4;          // 0..7  (h-tile load row base)
    const int c4 = (tid & 15) * 4;    // 0..60

    for (int t = 0; t < SS; ++t) {
        const float* hcur = (t & 1) ? g_hpong : g_hping;
        float*       hnxt = (t & 1) ? g_hping : g_hpong;
        float accR[4] = {0.f, 0.f, 0.f, 0.f};
        float accU[4] = {0.f, 0.f, 0.f, 0.f};

        for (int kc = 0; kc < HH; kc += 64) {
            // cooperative load of h[0:64][kc:kc+64] (bypass L1: cross-CTA data)
#pragma unroll
            for (int r = 0; r < 8; ++r) {
                float4 hv = __ldcg((const float4*)(hcur + (size_t)(r0 + r * 8) * HH + kc + c4));
                *(float4*)&sh[(r0 + r * 8) * 68 + c4] = hv;
            }
            __syncthreads();
#pragma unroll
            for (int k = 0; k < 64; k += 4) {
                float4 wr4 = *(const float4*)&wr_s[jl * 1028 + kc + k];
                float4 wu4 = *(const float4*)&wu_s[jl * 1028 + kc + k];
#pragma unroll
                for (int i = 0; i < 4; ++i) {
                    float4 h4 = *(const float4*)&sh[(bg * 4 + i) * 68 + k];
                    accR[i] += h4.x*wr4.x + h4.y*wr4.y + h4.z*wr4.z + h4.w*wr4.w;
                    accU[i] += h4.x*wu4.x + h4.y*wu4.y + h4.z*wu4.z + h4.w*wu4.w;
                }
            }
            __syncthreads();
        }

        // update h for this CTA's 4 b's x 1 j per thread
#pragma unroll
        for (int i = 0; i < 4; ++i) {
            int b = bg * 4 + i;
            size_t base = ((size_t)b * SS + t) * HH + j;
            float dr   = g_Dr[base];
            float dw   = g_Dw[base];
            float g    = g_G[b * SS + t];
            float hold = __ldcg(hcur + b * HH + j);
            float r  = 1.f / (1.f + expf(-(dr + accR[i] + burj)));
            float ht = tanhf(dw + r * (accU[i] + buj));
            float hnew = g * ht + (1.f - g) * hold;
            hnxt[b * HH + j] = hnew;
            hs_out[base] = hnew;
        }
        grid_sync((unsigned)(t + 1));
    }
}

// ---------------- final next_mem = relu([P, C, Q] @ Wm + bm) -----------------
__global__ void next_mem_kernel(const float* __restrict__ P,
                                const float* __restrict__ Q,
                                const float* __restrict__ Wm,
                                const float* __restrict__ bm,
                                float* __restrict__ out) {
    __shared__ float srow[H3];
    int b = blockIdx.x;
    int tid = threadIdx.x;  // 256
    for (int i = tid; i < HH; i += 256) {
        srow[i]            = P[b * HH + i];
        srow[HH + i]       = g_hping[b * HH + i];   // final h (S even -> ping)
        srow[2 * HH + i]   = Q[b * HH + i];
    }
    __syncthreads();
    float acc0 = bm[tid], acc1 = bm[tid + 256], acc2 = bm[tid + 512], acc3 = bm[tid + 768];
    for (int k = 0; k < H3; ++k) {
        float s = srow[k];
        const float* w = Wm + (size_t)k * HH + tid;
        acc0 += s * w[0];
        acc1 += s * w[256];
        acc2 += s * w[512];
        acc3 += s * w[768];
    }
    out[b * HH + tid]       = fmaxf(acc0, 0.f);
    out[b * HH + tid + 256] = fmaxf(acc1, 0.f);
    out[b * HH + tid + 512] = fmaxf(acc2, 0.f);
    out[b * HH + tid + 768] = fmaxf(acc3, 0.f);
}

// ---------------- launch ----------------------------------------------------
extern "C" void kernel_launch(void* const* d_in, const int* in_sizes, int n_in,
                              void* d_out, int out_size) {
    const float* D   = (const float*)d_in[0];
    const float* Q   = (const float*)d_in[1];
    const float* P   = (const float*)d_in[2];   // prev_mem
    const float* Wr  = (const float*)d_in[3];
    const float* br  = (const float*)d_in[4];
    const float* Ur  = (const float*)d_in[5];
    const float* bur = (const float*)d_in[6];
    const float* Wx  = (const float*)d_in[7];
    const float* bx  = (const float*)d_in[8];
    const float* U   = (const float*)d_in[9];
    const float* bu  = (const float*)d_in[10];
    const float* W1  = (const float*)d_in[11];
    const float* b1  = (const float*)d_in[12];
    const float* W2  = (const float*)d_in[13];
    const float* b2  = (const float*)d_in[14];
    const float* Wm  = (const float*)d_in[15];
    const float* bm  = (const float*)d_in[16];

    float* out_next = (float*)d_out;            // (B,1,H)
    float* out_hs   = (float*)d_out + BB * HH;  // (B,S,H)

    static int smem_set = 0;
    const int scan_smem = (16 * 1028 + 64 * 68) * 4;   // 83,200 B
    if (!smem_set) {
        cudaFuncSetAttribute(scan_kernel, cudaFuncAttributeMaxDynamicSharedMemorySize, scan_smem);
        smem_set = 1;
    }

    float *gz, *gh1, *gDr, *gDw, *gUrT, *gUT;
    cudaGetSymbolAddress((void**)&gz, g_z);
    cudaGetSymbolAddress((void**)&gh1, g_h1);
    cudaGetSymbolAddress((void**)&gDr, g_Dr);
    cudaGetSymbolAddress((void**)&gDw, g_Dw);
    cudaGetSymbolAddress((void**)&gUrT, g_UrT);
    cudaGetSymbolAddress((void**)&gUT, g_UT);

    // 1) z features
    build_z_kernel<<<MM * (HH/4) / 256, 256>>>(D, Q, P);
    // 2) h1 = tanh(z @ W1 + b1)
    sgemm128<<<dim3(HH/128, MM/128), 256>>>(gz, W1, b1, gh1, MM, HH, H4, 1);
    // 3) Zs = h1 @ W2 + b2 ; 4) softmax -> G
    zs_gemv_kernel<<<MM, 128>>>(W2, b2);
    softmax_kernel<<<BB, 256>>>();
    // 5) Dr, Dw
    sgemm128<<<dim3(HH/128, MM/128), 256>>>(D, Wr, br, gDr, MM, HH, HH, 0);
    sgemm128<<<dim3(HH/128, MM/128), 256>>>(D, Wx, bx, gDw, MM, HH, HH, 0);
    // 6) transpose recurrent weights for coalesced scan access
    transpose_kernel<<<dim3(32, 32), dim3(32, 8)>>>(Ur, gUrT);
    transpose_kernel<<<dim3(32, 32), dim3(32, 8)>>>(U, gUT);
    // 7) init h0 + barrier state
    init_kernel<<<256, 256>>>();
    // 8) sequential scan (persistent, 1 grid barrier per step)
    scan_kernel<<<NCTA_SCAN, 128, scan_smem>>>(bur, bu, out_hs);
    // 9) next_mem
    next_mem_kernel<<<BB, 256>>>(P, Q, Wm, bm, out_next);
}

// round 4
// speedup vs baseline: 1.3457x; 1.3446x over previous
#include <cuda_runtime.h>
#include <cuda_bf16.h>
#include <cstdint>
#include <math.h>

#define BB 64
#define SS 256
#define HH 1024
#define MM (BB*SS)
#define H4 (4*HH)
#define H3 (3*HH)
#define NCTA_SCAN 128
#define TS 40   // smem tile stride (bf16 units), pad 8

// scratch
__device__ __nv_bfloat16 g_zh[(size_t)MM * H4];
__device__ __nv_bfloat16 g_zl[(size_t)MM * H4];
__device__ __nv_bfloat16 g_dh[(size_t)MM * HH];
__device__ __nv_bfloat16 g_dl[(size_t)MM * HH];
__device__ __nv_bfloat16 g_w1th[(size_t)HH * H4];
__device__ __nv_bfloat16 g_w1tl[(size_t)HH * H4];
__device__ __nv_bfloat16 g_wrth[HH * HH];
__device__ __nv_bfloat16 g_wrtl[HH * HH];
__device__ __nv_bfloat16 g_wxth[HH * HH];
__device__ __nv_bfloat16 g_wxtl[HH * HH];
__device__ float g_h1[(size_t)MM * HH];
__device__ float g_Dr[(size_t)MM * HH];
__device__ float g_Dw[(size_t)MM * HH];
__device__ float g_Zs[MM];
__device__ float g_G[MM];
__device__ float g_UrT[HH * HH];
__device__ float g_UT[HH * HH];
__device__ float g_hping[BB * HH];
__device__ float g_hpong[BB * HH];
__device__ unsigned g_bar_count;
__device__ unsigned g_bar_gen;

// ---- helpers ----
__device__ __forceinline__ uint32_t smem_u32(const void* p) {
    uint32_t a;
    asm("{ .reg .u64 t; cvta.to.shared.u64 t, %1; cvt.u32.u64 %0, t; }" : "=r"(a) : "l"(p));
    return a;
}
__device__ __forceinline__ void cpasync16(uint32_t s, const void* g) {
    asm volatile("cp.async.cg.shared.global [%0], [%1], 16;" :: "r"(s), "l"(g));
}
#define CP_COMMIT() asm volatile("cp.async.commit_group;" ::: "memory")
#define CP_WAIT1()  asm volatile("cp.async.wait_group 1;" ::: "memory")

__device__ __forceinline__ void mma16816(float* c, const uint32_t* a, uint32_t b0, uint32_t b1) {
    asm volatile("mma.sync.aligned.m16n8k16.row.col.f32.bf16.bf16.f32 "
        "{%0,%1,%2,%3}, {%4,%5,%6,%7}, {%8,%9}, {%0,%1,%2,%3};"
        : "+f"(c[0]), "+f"(c[1]), "+f"(c[2]), "+f"(c[3])
        : "r"(a[0]), "r"(a[1]), "r"(a[2]), "r"(a[3]), "r"(b0), "r"(b1));
}

__device__ __forceinline__ void split_store4(float4 v, __nv_bfloat16* hp, __nv_bfloat16* lp) {
    __nv_bfloat16 h0=__float2bfloat16_rn(v.x), h1=__float2bfloat16_rn(v.y),
                  h2=__float2bfloat16_rn(v.z), h3=__float2bfloat16_rn(v.w);
    __nv_bfloat16 l0=__float2bfloat16_rn(v.x-__bfloat162float(h0)),
                  l1=__float2bfloat16_rn(v.y-__bfloat162float(h1)),
                  l2=__float2bfloat16_rn(v.z-__bfloat162float(h2)),
                  l3=__float2bfloat16_rn(v.w-__bfloat162float(h3));
    *(ushort4*)hp = make_ushort4(__bfloat16_as_ushort(h0),__bfloat16_as_ushort(h1),
                                 __bfloat16_as_ushort(h2),__bfloat16_as_ushort(h3));
    *(ushort4*)lp = make_ushort4(__bfloat16_as_ushort(l0),__bfloat16_as_ushort(l1),
                                 __bfloat16_as_ushort(l2),__bfloat16_as_ushort(l3));
}

// ---- z features hi/lo ----
__global__ void build_z_split(const float* __restrict__ D, const float* __restrict__ Q,
                              const float* __restrict__ P) {
    int idx = blockIdx.x * blockDim.x + threadIdx.x;
    if (idx >= MM * (HH/4)) return;
    int k4 = idx & 255, m = idx >> 8, b = m >> 8;
    float4 d = ((const float4*)D)[idx];
    float4 q = ((const float4*)Q)[(b << 8) + k4];
    float4 p = ((const float4*)P)[(b << 8) + k4];
    __nv_bfloat16* zh = g_zh + (size_t)m * H4;
    __nv_bfloat16* zl = g_zl + (size_t)m * H4;
    int c = k4 * 4;
    split_store4(make_float4(d.x*q.x,d.y*q.y,d.z*q.z,d.w*q.w), zh+c, zl+c);
    split_store4(make_float4(d.x*p.x,d.y*p.y,d.z*p.z,d.w*p.w), zh+HH+c, zl+HH+c);
    split_store4(make_float4(fabsf(d.x-q.x),fabsf(d.y-q.y),fabsf(d.z-q.z),fabsf(d.w-q.w)), zh+2*HH+c, zl+2*HH+c);
    split_store4(make_float4(fabsf(d.x-p.x),fabsf(d.y-p.y),fabsf(d.z-p.z),fabsf(d.w-p.w)), zh+3*HH+c, zl+3*HH+c);
}

__global__ void split_D_kernel(const float* __restrict__ D) {
    int idx = blockIdx.x * blockDim.x + threadIdx.x;
    if (idx >= MM * (HH/4)) return;
    split_store4(((const float4*)D)[idx], g_dh + (size_t)idx*4, g_dl + (size_t)idx*4);
}

// W[K][N] -> WT hi/lo [N][K]
__global__ void wtsplit_kernel(const float* __restrict__ W, __nv_bfloat16* __restrict__ Th,
                               __nv_bfloat16* __restrict__ Tl, int K, int N) {
    __shared__ float tile[32][33];
    int x = blockIdx.x*32 + threadIdx.x, y = blockIdx.y*32 + threadIdx.y;
#pragma unroll
    for (int i = 0; i < 4; ++i)
        tile[threadIdx.y + i*8][threadIdx.x] = W[(size_t)(y + i*8)*N + x];
    __syncthreads();
    int n = blockIdx.x*32 + threadIdx.y, k = blockIdx.y*32 + threadIdx.x;
#pragma unroll
    for (int i = 0; i < 4; ++i) {
        float v = tile[threadIdx.x][threadIdx.y + i*8];
        __nv_bfloat16 h = __float2bfloat16_rn(v);
        size_t o = (size_t)(n + i*8)*K + k;
        Th[o] = h;
        Tl[o] = __float2bfloat16_rn(v - __bfloat162float(h));
    }
}

__global__ void transpose_kernel(const float* __restrict__ src, float* __restrict__ dst) {
    __shared__ float tile[32][33];
    int x = blockIdx.x*32 + threadIdx.x, y = blockIdx.y*32 + threadIdx.y;
#pragma unroll
    for (int i = 0; i < 4; ++i)
        tile[threadIdx.y + i*8][threadIdx.x] = src[(size_t)(y + i*8)*HH + x];
    __syncthreads();
    x = blockIdx.y*32 + threadIdx.x; y = blockIdx.x*32 + threadIdx.y;
#pragma unroll
    for (int i = 0; i < 4; ++i)
        dst[(size_t)(y + i*8)*HH + x] = tile[threadIdx.x][threadIdx.y + i*8];
}

// ---- HMMA split-bf16 GEMM: C[M][N] = act(A @ B^T + bias) ----
// A hi/lo [M][K], BT hi/lo [N][K]. grid(N/128, M/128), 256 thr, 8 warps 4x2.
#define G_SMEM_BYTES (2 * 4 * 128 * TS * 2)   // 81920
__global__ __launch_bounds__(256, 2) void gemm_hmma(
        const __nv_bfloat16* __restrict__ Ah, const __nv_bfloat16* __restrict__ Al,
        const __nv_bfloat16* __restrict__ Bh, const __nv_bfloat16* __restrict__ Bl,
        const float* __restrict__ bias, float* __restrict__ C,
        int M, int N, int K, int act) {
    extern __shared__ __nv_bfloat16 sm[];
    const int tid = threadIdx.x, wid = tid >> 5, lane = tid & 31;
    const int wm = wid >> 1, wn = wid & 1;
    const int g = lane >> 2, t = lane & 3;
    const int bm = blockIdx.y * 128, bn = blockIdx.x * 128;
    const int BUF = 4 * 128 * TS;

    float acc[2][8][4];
#pragma unroll
    for (int i = 0; i < 2; ++i)
#pragma unroll
        for (int j = 0; j < 8; ++j)
#pragma unroll
            for (int q = 0; q < 4; ++q) acc[i][j][q] = 0.f;

    // cp.async indices: per thread 2 (row,seg) pairs per array
    const int r0l = (tid*2) >> 3, s0l = (tid*2) & 7;   // idx = tid*2 .. tid*2+1 -> r=idx>>2? careful
    // simpler: idx0 = tid, idx1 = tid+256 over 512 pairs; r = idx>>2, seg = idx&3
    const int rA = tid >> 2, sA = tid & 3;
    const int rB = (tid + 256) >> 2, sB = (tid + 256) & 3;
    (void)r0l; (void)s0l;

    const int nch = K >> 5;
    uint32_t smb = smem_u32(sm);

    // prefetch chunk 0
    {
        const size_t k0 = 0;
#pragma unroll
        for (int p = 0; p < 2; ++p) {
            int r = p ? rB : rA, s = p ? sB : sA;
            uint32_t so = (uint32_t)((r*TS + s*8) * 2);
            size_t ga = (size_t)(bm + r)*K + k0 + s*8;
            size_t gb = (size_t)(bn + r)*K + k0 + s*8;
            cpasync16(smb + so,                     Ah + ga);
            cpasync16(smb + 128*TS*2 + so,          Al + ga);
            cpasync16(smb + 2*128*TS*2 + so,        Bh + gb);
            cpasync16(smb + 3*128*TS*2 + so,        Bl + gb);
        }
    }
    CP_COMMIT();

    for (int c = 0; c < nch; ++c) {
        if (c + 1 < nch) {
            const size_t k0 = (size_t)(c + 1) * 32;
            uint32_t bufo = (uint32_t)(((c + 1) & 1) * BUF * 2);
#pragma unroll
            for (int p = 0; p < 2; ++p) {
                int r = p ? rB : rA, s = p ? sB : sA;
                uint32_t so = bufo + (uint32_t)((r*TS + s*8) * 2);
                size_t ga = (size_t)(bm + r)*K + k0 + s*8;
                size_t gb = (size_t)(bn + r)*K + k0 + s*8;
                cpasync16(smb + so,              Ah + ga);
                cpasync16(smb + 128*TS*2 + so,   Al + ga);
                cpasync16(smb + 2*128*TS*2 + so, Bh + gb);
                cpasync16(smb + 3*128*TS*2 + so, Bl + gb);
            }
        }
        CP_COMMIT();
        CP_WAIT1();
        __syncthreads();

        const __nv_bfloat16* bs = sm + (c & 1) * BUF;
        const __nv_bfloat16* sAh = bs;
        const __nv_bfloat16* sAl = bs + 128*TS;
        const __nv_bfloat16* sBh = bs + 2*128*TS;
        const __nv_bfloat16* sBl = bs + 3*128*TS;

#pragma unroll
        for (int kk = 0; kk < 32; kk += 16) {
            uint32_t ah[2][4], al[2][4];
#pragma unroll
            for (int i = 0; i < 2; ++i) {
                int row = wm*32 + i*16 + g;
                const __nv_bfloat16* pah = sAh + row*TS + kk + 2*t;
                const __nv_bfloat16* pal = sAl + row*TS + kk + 2*t;
                ah[i][0] = *(const uint32_t*)(pah);
                ah[i][1] = *(const uint32_t*)(pah + 8*TS);
                ah[i][2] = *(const uint32_t*)(pah + 8);
                ah[i][3] = *(const uint32_t*)(pah + 8*TS + 8);
                al[i][0] = *(const uint32_t*)(pal);
                al[i][1] = *(const uint32_t*)(pal + 8*TS);
                al[i][2] = *(const uint32_t*)(pal + 8);
                al[i][3] = *(const uint32_t*)(pal + 8*TS + 8);
            }
#pragma unroll
            for (int j = 0; j < 8; ++j) {
                int col = wn*64 + j*8 + g;
                const __nv_bfloat16* pbh = sBh + col*TS + kk + 2*t;
                const __nv_bfloat16* pbl = sBl + col*TS + kk + 2*t;
                uint32_t bh0 = *(const uint32_t*)(pbh);
                uint32_t bh1 = *(const uint32_t*)(pbh + 8);
                uint32_t bl0 = *(const uint32_t*)(pbl);
                uint32_t bl1 = *(const uint32_t*)(pbl + 8);
#pragma unroll
                for (int i = 0; i < 2; ++i) {
                    mma16816(acc[i][j], ah[i], bh0, bh1);
                    mma16816(acc[i][j], ah[i], bl0, bl1);
                    mma16816(acc[i][j], al[i], bh0, bh1);
                }
            }
        }
        __syncthreads();
    }

    // epilogue: c0=C[g][2t], c1=C[g][2t+1], c2=C[g+8][2t], c3=C[g+8][2t+1]
#pragma unroll
    for (int i = 0; i < 2; ++i) {
#pragma unroll
        for (int j = 0; j < 8; ++j) {
            int row = bm + wm*32 + i*16 + g;
            int col = bn + wn*64 + j*8 + 2*t;
            float b0 = bias[col], b1 = bias[col+1];
            float v0 = acc[i][j][0] + b0, v1 = acc[i][j][1] + b1;
            float v2 = acc[i][j][2] + b0, v3 = acc[i][j][3] + b1;
            if (act) { v0=tanhf(v0); v1=tanhf(v1); v2=tanhf(v2); v3=tanhf(v3); }
            *(float2*)(C + (size_t)row*N + col)       = make_float2(v0, v1);
            *(float2*)(C + (size_t)(row+8)*N + col)   = make_float2(v2, v3);
        }
    }
}

// ---- Zs GEMV + softmax ----
__global__ void zs_gemv_kernel(const float* __restrict__ W2, const float* __restrict__ b2) {
    int m = blockIdx.x, tid = threadIdx.x;
    const float4* hr = (const float4*)(g_h1 + (size_t)m * HH);
    const float4* w = (const float4*)W2;
    float s = 0.f;
#pragma unroll
    for (int k = tid; k < 256; k += 128) {
        float4 a = hr[k], bb = w[k];
        s += a.x*bb.x + a.y*bb.y + a.z*bb.z + a.w*bb.w;
    }
#pragma unroll
    for (int off = 16; off; off >>= 1) s += __shfl_down_sync(0xffffffffu, s, off);
    __shared__ float ws[4];
    if ((tid & 31) == 0) ws[tid >> 5] = s;
    __syncthreads();
    if (tid == 0) g_Zs[m] = ws[0] + ws[1] + ws[2] + ws[3] + b2[0];
}

__global__ void softmax_kernel() {
    int b = blockIdx.x, tid = threadIdx.x;
    __shared__ float red[256];
    float v = g_Zs[b * SS + tid];
    red[tid] = v; __syncthreads();
#pragma unroll
    for (int off = 128; off; off >>= 1) {
        if (tid < off) red[tid] = fmaxf(red[tid], red[tid + off]);
        __syncthreads();
    }
    float mx = red[0]; __syncthreads();
    float e = expf(v - mx);
    red[tid] = e; __syncthreads();
#pragma unroll
    for (int off = 128; off; off >>= 1) {
        if (tid < off) red[tid] += red[tid + off];
        __syncthreads();
    }
    g_G[b * SS + tid] = e / red[0];
}

__global__ void init_kernel() {
    int i = blockIdx.x * blockDim.x + threadIdx.x;
    if (i < BB * HH) g_hping[i] = 0.f;
    if (i == 0) { g_bar_count = 0u; g_bar_gen = 0u; }
}

__device__ __forceinline__ void grid_sync(unsigned target) {
    __syncthreads();
    if (threadIdx.x == 0) {
        __threadfence();
        unsigned prev = atomicAdd(&g_bar_count, 1u);
        if (prev == NCTA_SCAN - 1) {
            g_bar_count = 0u;
            __threadfence();
            atomicExch(&g_bar_gen, target);
        } else {
            while (*((volatile unsigned*)&g_bar_gen) < target) { __nanosleep(64); }
        }
        __threadfence();
    }
    __syncthreads();
}

// ---- persistent scan ----
__global__ __launch_bounds__(128) void scan_kernel(const float* __restrict__ bur,
                                                   const float* __restrict__ bu,
                                                   float* __restrict__ hs_out) {
    extern __shared__ float smf[];
    float* wr_s = smf;
    float* wu_s = smf + 8 * 1028;
    float* sh   = smf + 16 * 1028;   // [64][68]
    const int tid = threadIdx.x;
    const int jl = tid & 7, bg = tid >> 3;
    const int j = blockIdx.x * 8 + jl;

    for (int idx = tid; idx < 2048; idx += 128) {
        int jj = idx >> 8, k4 = idx & 255;
        *(float4*)&wr_s[jj*1028 + k4*4] = *(const float4*)(g_UrT + (size_t)(blockIdx.x*8+jj)*HH + k4*4);
        *(float4*)&wu_s[jj*1028 + k4*4] = *(const float4*)(g_UT  + (size_t)(blockIdx.x*8+jj)*HH + k4*4);
    }
    const float burj = bur[j], buj = bu[j];
    __syncthreads();

    const int r0 = tid >> 4, c4 = (tid & 15) * 4;

    for (int t = 0; t < SS; ++t) {
        const float* hcur = (t & 1) ? g_hpong : g_hping;
        float*       hnxt = (t & 1) ? g_hping : g_hpong;
        float accR[4] = {0,0,0,0}, accU[4] = {0,0,0,0};

        for (int kc = 0; kc < HH; kc += 64) {
#pragma unroll
            for (int r = 0; r < 8; ++r) {
                float4 hv = __ldcg((const float4*)(hcur + (size_t)(r0 + r*8)*HH + kc + c4));
                *(float4*)&sh[(r0 + r*8)*68 + c4] = hv;
            }
            __syncthreads();
#pragma unroll
            for (int k = 0; k < 64; k += 4) {
                float4 wr4 = *(const float4*)&wr_s[jl*1028 + kc + k];
                float4 wu4 = *(const float4*)&wu_s[jl*1028 + kc + k];
#pragma unroll
                for (int i = 0; i < 4; ++i) {
                    float4 h4 = *(const float4*)&sh[(bg + i*16)*68 + k];
                    accR[i] += h4.x*wr4.x + h4.y*wr4.y + h4.z*wr4.z + h4.w*wr4.w;
                    accU[i] += h4.x*wu4.x + h4.y*wu4.y + h4.z*wu4.z + h4.w*wu4.w;
                }
            }
            __syncthreads();
        }
#pragma unroll
        for (int i = 0; i < 4; ++i) {
            int b = bg + i * 16;
            size_t base = ((size_t)b * SS + t) * HH + j;
            float dr = g_Dr[base], dw = g_Dw[base], gg = g_G[b*SS + t];
            float hold = __ldcg(hcur + b*HH + j);
            float r  = 1.f / (1.f + expf(-(dr + accR[i] + burj)));
            float ht = tanhf(dw + r * (accU[i] + buj));
            float hnew = gg * ht + (1.f - gg) * hold;
            hnxt[b*HH + j] = hnew;
            hs_out[base] = hnew;
        }
        grid_sync((unsigned)(t + 1));
    }
}

// ---- next_mem ----
__global__ void next_mem_kernel(const float* __restrict__ P, const float* __restrict__ Q,
                                const float* __restrict__ Wm, const float* __restrict__ bm,
                                float* __restrict__ out) {
    __shared__ float srow[H3];
    int b = blockIdx.x, tid = threadIdx.x;
    for (int i = tid; i < HH; i += 256) {
        srow[i]        = P[b*HH + i];
        srow[HH + i]   = g_hping[b*HH + i];
        srow[2*HH + i] = Q[b*HH + i];
    }
    __syncthreads();
    float a0 = bm[tid], a1 = bm[tid+256], a2 = bm[tid+512], a3 = bm[tid+768];
    for (int k = 0; k < H3; ++k) {
        float s = srow[k];
        const float* w = Wm + (size_t)k*HH + tid;
        a0 += s*w[0]; a1 += s*w[256]; a2 += s*w[512]; a3 += s*w[768];
    }
    out[b*HH+tid]     = fmaxf(a0, 0.f);
    out[b*HH+tid+256] = fmaxf(a1, 0.f);
    out[b*HH+tid+512] = fmaxf(a2, 0.f);
    out[b*HH+tid+768] = fmaxf(a3, 0.f);
}

extern "C" void kernel_launch(void* const* d_in, const int* in_sizes, int n_in,
                              void* d_out, int out_size) {
    const float* D   = (const float*)d_in[0];
    const float* Q   = (const float*)d_in[1];
    const float* P   = (const float*)d_in[2];
    const float* Wr  = (const float*)d_in[3];
    const float* br  = (const float*)d_in[4];
    const float* Ur  = (const float*)d_in[5];
    const float* bur = (const float*)d_in[6];
    const float* Wx  = (const float*)d_in[7];
    const float* bx  = (const float*)d_in[8];
    const float* U   = (const float*)d_in[9];
    const float* bu  = (const float*)d_in[10];
    const float* W1  = (const float*)d_in[11];
    const float* b1  = (const float*)d_in[12];
    const float* W2  = (const float*)d_in[13];
    const float* b2  = (const float*)d_in[14];
    const float* Wm  = (const float*)d_in[15];
    const float* bm  = (const float*)d_in[16];

    float* out_next = (float*)d_out;
    float* out_hs   = (float*)d_out + BB * HH;

    static int attr_set = 0;
    const int scan_smem = (16 * 1028 + 64 * 68) * 4;
    if (!attr_set) {
        cudaFuncSetAttribute(scan_kernel, cudaFuncAttributeMaxDynamicSharedMemorySize, scan_smem);
        cudaFuncSetAttribute(gemm_hmma, cudaFuncAttributeMaxDynamicSharedMemorySize, G_SMEM_BYTES);
        attr_set = 1;
    }

    __nv_bfloat16 *zh, *zl, *dh, *dl, *w1th, *w1tl, *wrth, *wrtl, *wxth, *wxtl;
    float *gh1, *gDr, *gDw, *gUrT, *gUT;
    cudaGetSymbolAddress((void**)&zh, g_zh);
    cudaGetSymbolAddress((void**)&zl, g_zl);
    cudaGetSymbolAddress((void**)&dh, g_dh);
    cudaGetSymbolAddress((void**)&dl, g_dl);
    cudaGetSymbolAddress((void**)&w1th, g_w1th);
    cudaGetSymbolAddress((void**)&w1tl, g_w1tl);
    cudaGetSymbolAddress((void**)&wrth, g_wrth);
    cudaGetSymbolAddress((void**)&wrtl, g_wrtl);
    cudaGetSymbolAddress((void**)&wxth, g_wxth);
    cudaGetSymbolAddress((void**)&wxtl, g_wxtl);
    cudaGetSymbolAddress((void**)&gh1, g_h1);
    cudaGetSymbolAddress((void**)&gDr, g_Dr);
    cudaGetSymbolAddress((void**)&gDw, g_Dw);
    cudaGetSymbolAddress((void**)&gUrT, g_UrT);
    cudaGetSymbolAddress((void**)&gUT, g_UT);

    build_z_split<<<MM*(HH/4)/256, 256>>>(D, Q, P);
    split_D_kernel<<<MM*(HH/4)/256, 256>>>(D);
    wtsplit_kernel<<<dim3(HH/32, H4/32), dim3(32, 8)>>>(W1, w1th, w1tl, H4, HH);
    wtsplit_kernel<<<dim3(HH/32, HH/32), dim3(32, 8)>>>(Wr, wrth, wrtl, HH, HH);
    wtsplit_kernel<<<dim3(HH/32, HH/32), dim3(32, 8)>>>(Wx, wxth, wxtl, HH, HH);

    gemm_hmma<<<dim3(HH/128, MM/128), 256, G_SMEM_BYTES>>>(zh, zl, w1th, w1tl, b1, gh1, MM, HH, H4, 1);
    zs_gemv_kernel<<<MM, 128>>>(W2, b2);
    softmax_kernel<<<BB, 256>>>();
    gemm_hmma<<<dim3(HH/128, MM/128), 256, G_SMEM_BYTES>>>(dh, dl, wrth, wrtl, br, gDr, MM, HH, HH, 0);
    gemm_hmma<<<dim3(HH/128, MM/128), 256, G_SMEM_BYTES>>>(dh, dl, wxth, wxtl, bx, gDw, MM, HH, HH, 0);

    transpose_kernel<<<dim3(32, 32), dim3(32, 8)>>>(Ur, gUrT);
    transpose_kernel<<<dim3(32, 32), dim3(32, 8)>>>(U, gUT);
    init_kernel<<<256, 256>>>();
    scan_kernel<<<NCTA_SCAN, 128, scan_smem>>>(bur, bu, out_hs);
    next_mem_kernel<<<BB, 256>>>(P, Q, Wm, bm, out_next);
}

// round 5
// speedup vs baseline: 1.7704x; 1.3156x over previous
#include <cuda_runtime.h>
#include <cuda_bf16.h>
#include <cstdint>
#include <math.h>

#define BB 64
#define SS 256
#define HH 1024
#define MM (BB*SS)
#define H4 (4*HH)
#define H3 (3*HH)
#define NCTA_SCAN 128
#define TS 40   // gemm smem tile stride (bf16), pad 8

__device__ __nv_bfloat16 g_zh[(size_t)MM * H4];
__device__ __nv_bfloat16 g_zl[(size_t)MM * H4];
__device__ __nv_bfloat16 g_dh[(size_t)MM * HH];
__device__ __nv_bfloat16 g_dl[(size_t)MM * HH];
__device__ __nv_bfloat16 g_w1th[(size_t)HH * H4];
__device__ __nv_bfloat16 g_w1tl[(size_t)HH * H4];
__device__ __nv_bfloat16 g_wrth[HH * HH];
__device__ __nv_bfloat16 g_wrtl[HH * HH];
__device__ __nv_bfloat16 g_wxth[HH * HH];
__device__ __nv_bfloat16 g_wxtl[HH * HH];
__device__ float g_h1[(size_t)MM * HH];
__device__ float g_Dr[(size_t)MM * HH];
__device__ float g_Dw[(size_t)MM * HH];
__device__ float g_Zs[MM];
__device__ float g_G[MM];
__device__ float g_UrT[HH * HH];
__device__ float g_UT[HH * HH];
__device__ float g_hping[BB * HH];
__device__ float g_hpong[BB * HH];
__device__ unsigned g_bar_count;
__device__ unsigned g_bar_gen;

// ---- helpers ----
__device__ __forceinline__ uint32_t smem_u32(const void* p) {
    uint32_t a;
    asm("{ .reg .u64 t; cvta.to.shared.u64 t, %1; cvt.u32.u64 %0, t; }" : "=r"(a) : "l"(p));
    return a;
}
__device__ __forceinline__ void cpasync16(uint32_t s, const void* g) {
    asm volatile("cp.async.cg.shared.global [%0], [%1], 16;" :: "r"(s), "l"(g));
}
#define CP_COMMIT() asm volatile("cp.async.commit_group;" ::: "memory")
#define CP_WAIT1()  asm volatile("cp.async.wait_group 1;" ::: "memory")

__device__ __forceinline__ void mma16816(float* c, const uint32_t* a, uint32_t b0, uint32_t b1) {
    asm volatile("mma.sync.aligned.m16n8k16.row.col.f32.bf16.bf16.f32 "
        "{%0,%1,%2,%3}, {%4,%5,%6,%7}, {%8,%9}, {%0,%1,%2,%3};"
        : "+f"(c[0]), "+f"(c[1]), "+f"(c[2]), "+f"(c[3])
        : "r"(a[0]), "r"(a[1]), "r"(a[2]), "r"(a[3]), "r"(b0), "r"(b1));
}

__device__ __forceinline__ void split_store4(float4 v, __nv_bfloat16* hp, __nv_bfloat16* lp) {
    __nv_bfloat16 h0=__float2bfloat16_rn(v.x), h1=__float2bfloat16_rn(v.y),
                  h2=__float2bfloat16_rn(v.z), h3=__float2bfloat16_rn(v.w);
    __nv_bfloat16 l0=__float2bfloat16_rn(v.x-__bfloat162float(h0)),
                  l1=__float2bfloat16_rn(v.y-__bfloat162float(h1)),
                  l2=__float2bfloat16_rn(v.z-__bfloat162float(h2)),
                  l3=__float2bfloat16_rn(v.w-__bfloat162float(h3));
    *(ushort4*)hp = make_ushort4(__bfloat16_as_ushort(h0),__bfloat16_as_ushort(h1),
                                 __bfloat16_as_ushort(h2),__bfloat16_as_ushort(h3));
    *(ushort4*)lp = make_ushort4(__bfloat16_as_ushort(l0),__bfloat16_as_ushort(l1),
                                 __bfloat16_as_ushort(l2),__bfloat16_as_ushort(l3));
}

// ---- z features hi/lo + D hi/lo (merged) ----
__global__ void build_feats(const float* __restrict__ D, const float* __restrict__ Q,
                            const float* __restrict__ P) {
    int idx = blockIdx.x * blockDim.x + threadIdx.x;
    if (idx >= MM * (HH/4)) return;
    int k4 = idx & 255, m = idx >> 8, b = m >> 8;
    float4 d = ((const float4*)D)[idx];
    float4 q = ((const float4*)Q)[(b << 8) + k4];
    float4 p = ((const float4*)P)[(b << 8) + k4];
    __nv_bfloat16* zh = g_zh + (size_t)m * H4;
    __nv_bfloat16* zl = g_zl + (size_t)m * H4;
    int c = k4 * 4;
    split_store4(make_float4(d.x*q.x,d.y*q.y,d.z*q.z,d.w*q.w), zh+c, zl+c);
    split_store4(make_float4(d.x*p.x,d.y*p.y,d.z*p.z,d.w*p.w), zh+HH+c, zl+HH+c);
    split_store4(make_float4(fabsf(d.x-q.x),fabsf(d.y-q.y),fabsf(d.z-q.z),fabsf(d.w-q.w)), zh+2*HH+c, zl+2*HH+c);
    split_store4(make_float4(fabsf(d.x-p.x),fabsf(d.y-p.y),fabsf(d.z-p.z),fabsf(d.w-p.w)), zh+3*HH+c, zl+3*HH+c);
    split_store4(d, g_dh + (size_t)idx*4, g_dl + (size_t)idx*4);
}

// W[K][N] -> WT hi/lo [N][K]
__global__ void wtsplit_kernel(const float* __restrict__ W, __nv_bfloat16* __restrict__ Th,
                               __nv_bfloat16* __restrict__ Tl, int K, int N) {
    __shared__ float tile[32][33];
    int x = blockIdx.x*32 + threadIdx.x, y = blockIdx.y*32 + threadIdx.y;
#pragma unroll
    for (int i = 0; i < 4; ++i)
        tile[threadIdx.y + i*8][threadIdx.x] = W[(size_t)(y + i*8)*N + x];
    __syncthreads();
    int n = blockIdx.x*32 + threadIdx.y, k = blockIdx.y*32 + threadIdx.x;
#pragma unroll
    for (int i = 0; i < 4; ++i) {
        float v = tile[threadIdx.x][threadIdx.y + i*8];
        __nv_bfloat16 h = __float2bfloat16_rn(v);
        size_t o = (size_t)(n + i*8)*K + k;
        Th[o] = h;
        Tl[o] = __float2bfloat16_rn(v - __bfloat162float(h));
    }
}

__global__ void transpose_kernel(const float* __restrict__ src, float* __restrict__ dst) {
    __shared__ float tile[32][33];
    int x = blockIdx.x*32 + threadIdx.x, y = blockIdx.y*32 + threadIdx.y;
#pragma unroll
    for (int i = 0; i < 4; ++i)
        tile[threadIdx.y + i*8][threadIdx.x] = src[(size_t)(y + i*8)*HH + x];
    __syncthreads();
    x = blockIdx.y*32 + threadIdx.x; y = blockIdx.x*32 + threadIdx.y;
#pragma unroll
    for (int i = 0; i < 4; ++i)
        dst[(size_t)(y + i*8)*HH + x] = tile[threadIdx.x][threadIdx.y + i*8];
}

// ---- HMMA split-bf16 GEMM (as R4) ----
#define G_SMEM_BYTES (2 * 4 * 128 * TS * 2)
__global__ __launch_bounds__(256, 2) void gemm_hmma(
        const __nv_bfloat16* __restrict__ Ah, const __nv_bfloat16* __restrict__ Al,
        const __nv_bfloat16* __restrict__ Bh, const __nv_bfloat16* __restrict__ Bl,
        const float* __restrict__ bias, float* __restrict__ C,
        int M, int N, int K, int act) {
    extern __shared__ __nv_bfloat16 sm[];
    const int tid = threadIdx.x, wid = tid >> 5, lane = tid & 31;
    const int wm = wid >> 1, wn = wid & 1;
    const int g = lane >> 2, t = lane & 3;
    const int bm = blockIdx.y * 128, bn = blockIdx.x * 128;
    const int BUF = 4 * 128 * TS;

    float acc[2][8][4];
#pragma unroll
    for (int i = 0; i < 2; ++i)
#pragma unroll
        for (int j = 0; j < 8; ++j)
#pragma unroll
            for (int q = 0; q < 4; ++q) acc[i][j][q] = 0.f;

    const int rA = tid >> 2, sA = tid & 3;
    const int rB = (tid + 256) >> 2, sB = (tid + 256) & 3;
    const int nch = K >> 5;
    uint32_t smb = smem_u32(sm);

    {
#pragma unroll
        for (int p = 0; p < 2; ++p) {
            int r = p ? rB : rA, s = p ? sB : sA;
            uint32_t so = (uint32_t)((r*TS + s*8) * 2);
            size_t ga = (size_t)(bm + r)*K + s*8;
            size_t gb = (size_t)(bn + r)*K + s*8;
            cpasync16(smb + so,              Ah + ga);
            cpasync16(smb + 128*TS*2 + so,   Al + ga);
            cpasync16(smb + 2*128*TS*2 + so, Bh + gb);
            cpasync16(smb + 3*128*TS*2 + so, Bl + gb);
        }
    }
    CP_COMMIT();

    for (int c = 0; c < nch; ++c) {
        if (c + 1 < nch) {
            const size_t k0 = (size_t)(c + 1) * 32;
            uint32_t bufo = (uint32_t)(((c + 1) & 1) * BUF * 2);
#pragma unroll
            for (int p = 0; p < 2; ++p) {
                int r = p ? rB : rA, s = p ? sB : sA;
                uint32_t so = bufo + (uint32_t)((r*TS + s*8) * 2);
                size_t ga = (size_t)(bm + r)*K + k0 + s*8;
                size_t gb = (size_t)(bn + r)*K + k0 + s*8;
                cpasync16(smb + so,              Ah + ga);
                cpasync16(smb + 128*TS*2 + so,   Al + ga);
                cpasync16(smb + 2*128*TS*2 + so, Bh + gb);
                cpasync16(smb + 3*128*TS*2 + so, Bl + gb);
            }
        }
        CP_COMMIT();
        CP_WAIT1();
        __syncthreads();

        const __nv_bfloat16* bs = sm + (c & 1) * BUF;
        const __nv_bfloat16* sAh = bs;
        const __nv_bfloat16* sAl = bs + 128*TS;
        const __nv_bfloat16* sBh = bs + 2*128*TS;
        const __nv_bfloat16* sBl = bs + 3*128*TS;

#pragma unroll
        for (int kk = 0; kk < 32; kk += 16) {
            uint32_t ah[2][4], al[2][4];
#pragma unroll
            for (int i = 0; i < 2; ++i) {
                int row = wm*32 + i*16 + g;
                const __nv_bfloat16* pah = sAh + row*TS + kk + 2*t;
                const __nv_bfloat16* pal = sAl + row*TS + kk + 2*t;
                ah[i][0] = *(const uint32_t*)(pah);
                ah[i][1] = *(const uint32_t*)(pah + 8*TS);
                ah[i][2] = *(const uint32_t*)(pah + 8);
                ah[i][3] = *(const uint32_t*)(pah + 8*TS + 8);
                al[i][0] = *(const uint32_t*)(pal);
                al[i][1] = *(const uint32_t*)(pal + 8*TS);
                al[i][2] = *(const uint32_t*)(pal + 8);
                al[i][3] = *(const uint32_t*)(pal + 8*TS + 8);
            }
#pragma unroll
            for (int j = 0; j < 8; ++j) {
                int col = wn*64 + j*8 + g;
                const __nv_bfloat16* pbh = sBh + col*TS + kk + 2*t;
                const __nv_bfloat16* pbl = sBl + col*TS + kk + 2*t;
                uint32_t bh0 = *(const uint32_t*)(pbh);
                uint32_t bh1 = *(const uint32_t*)(pbh + 8);
                uint32_t bl0 = *(const uint32_t*)(pbl);
                uint32_t bl1 = *(const uint32_t*)(pbl + 8);
#pragma unroll
                for (int i = 0; i < 2; ++i) {
                    mma16816(acc[i][j], ah[i], bh0, bh1);
                    mma16816(acc[i][j], ah[i], bl0, bl1);
                    mma16816(acc[i][j], al[i], bh0, bh1);
                }
            }
        }
        __syncthreads();
    }

#pragma unroll
    for (int i = 0; i < 2; ++i) {
#pragma unroll
        for (int j = 0; j < 8; ++j) {
            int row = bm + wm*32 + i*16 + g;
            int col = bn + wn*64 + j*8 + 2*t;
            float b0 = bias[col], b1 = bias[col+1];
            float v0 = acc[i][j][0] + b0, v1 = acc[i][j][1] + b1;
            float v2 = acc[i][j][2] + b0, v3 = acc[i][j][3] + b1;
            if (act) { v0=tanhf(v0); v1=tanhf(v1); v2=tanhf(v2); v3=tanhf(v3); }
            *(float2*)(C + (size_t)row*N + col)     = make_float2(v0, v1);
            *(float2*)(C + (size_t)(row+8)*N + col) = make_float2(v2, v3);
        }
    }
}

// ---- Zs GEMV + softmax ----
__global__ void zs_gemv_kernel(const float* __restrict__ W2, const float* __restrict__ b2) {
    int m = blockIdx.x, tid = threadIdx.x;
    const float4* hr = (const float4*)(g_h1 + (size_t)m * HH);
    const float4* w = (const float4*)W2;
    float s = 0.f;
#pragma unroll
    for (int k = tid; k < 256; k += 128) {
        float4 a = hr[k], bb = w[k];
        s += a.x*bb.x + a.y*bb.y + a.z*bb.z + a.w*bb.w;
    }
#pragma unroll
    for (int off = 16; off; off >>= 1) s += __shfl_down_sync(0xffffffffu, s, off);
    __shared__ float ws[4];
    if ((tid & 31) == 0) ws[tid >> 5] = s;
    __syncthreads();
    if (tid == 0) g_Zs[m] = ws[0] + ws[1] + ws[2] + ws[3] + b2[0];
}

__global__ void softmax_kernel() {
    int b = blockIdx.x, tid = threadIdx.x;
    __shared__ float red[256];
    float v = g_Zs[b * SS + tid];
    red[tid] = v; __syncthreads();
#pragma unroll
    for (int off = 128; off; off >>= 1) {
        if (tid < off) red[tid] = fmaxf(red[tid], red[tid + off]);
        __syncthreads();
    }
    float mx = red[0]; __syncthreads();
    float e = expf(v - mx);
    red[tid] = e; __syncthreads();
#pragma unroll
    for (int off = 128; off; off >>= 1) {
        if (tid < off) red[tid] += red[tid + off];
        __syncthreads();
    }
    g_G[b * SS + tid] = e / red[0];
}

__global__ void init_kernel() {
    int i = blockIdx.x * blockDim.x + threadIdx.x;
    if (i < BB * HH) g_hping[i] = 0.f;
    if (i == 0) { g_bar_count = 0u; g_bar_gen = 0u; }
}

__device__ __forceinline__ void grid_sync(unsigned target) {
    __syncthreads();
    if (threadIdx.x == 0) {
        __threadfence();
        unsigned prev = atomicAdd(&g_bar_count, 1u);
        if (prev == NCTA_SCAN - 1) {
            g_bar_count = 0u;
            __threadfence();
            atomicExch(&g_bar_gen, target);
        } else {
            while (*((volatile unsigned*)&g_bar_gen) < target) { __nanosleep(32); }
        }
        __threadfence();
    }
    __syncthreads();
}

// ---- persistent scan: cp.async double-buffered h-chunks ----
// smem: wr[8][1028], wu[8][1028], sh[2][64][68]
#define SCAN_SMEM ((16*1028 + 2*64*68) * 4)
__global__ __launch_bounds__(128) void scan_kernel(const float* __restrict__ bur,
                                                   const float* __restrict__ bu,
                                                   float* __restrict__ hs_out) {
    extern __shared__ float smf[];
    float* wr_s = smf;
    float* wu_s = smf + 8 * 1028;
    float* sh   = smf + 16 * 1028;   // [2][64][68]
    const int tid = threadIdx.x;
    const int jl = tid & 7, bg = tid >> 3;
    const int j = blockIdx.x * 8 + jl;

    for (int idx = tid; idx < 2048; idx += 128) {
        int jj = idx >> 8, k4 = idx & 255;
        *(float4*)&wr_s[jj*1028 + k4*4] = *(const float4*)(g_UrT + (size_t)(blockIdx.x*8+jj)*HH + k4*4);
        *(float4*)&wu_s[jj*1028 + k4*4] = *(const float4*)(g_UT  + (size_t)(blockIdx.x*8+jj)*HH + k4*4);
    }
    const float burj = bur[j], buj = bu[j];
    __syncthreads();

    const int r0 = tid >> 4, c4 = (tid & 15) * 4;   // 8 rows per thread, 4-float col
    const uint32_t shb = smem_u32(sh);

    for (int t = 0; t < SS; ++t) {
        const float* hcur = (t & 1) ? g_hpong : g_hping;
        float*       hnxt = (t & 1) ? g_hping : g_hpong;
        float accR[4] = {0,0,0,0}, accU[4] = {0,0,0,0};

        // prefetch chunk 0 into buf 0
#pragma unroll
        for (int r = 0; r < 8; ++r)
            cpasync16(shb + ((r0 + r*8)*68 + c4)*4,
                      hcur + (size_t)(r0 + r*8)*HH + c4);
        CP_COMMIT();

        for (int c = 0; c < 16; ++c) {
            if (c + 1 < 16) {
                int kcn = (c + 1) * 64;
                uint32_t bo = (uint32_t)(((c + 1) & 1) * 64 * 68 * 4);
#pragma unroll
                for (int r = 0; r < 8; ++r)
                    cpasync16(shb + bo + ((r0 + r*8)*68 + c4)*4,
                              hcur + (size_t)(r0 + r*8)*HH + kcn + c4);
            }
            CP_COMMIT();
            CP_WAIT1();
            __syncthreads();

            const float* shc = sh + (c & 1) * 64 * 68;
            const int kc = c * 64;
#pragma unroll
            for (int k = 0; k < 64; k += 4) {
                float4 wr4 = *(const float4*)&wr_s[jl*1028 + kc + k];
                float4 wu4 = *(const float4*)&wu_s[jl*1028 + kc + k];
#pragma unroll
                for (int i = 0; i < 4; ++i) {
                    float4 h4 = *(const float4*)&shc[(bg + i*16)*68 + k];
                    accR[i] += h4.x*wr4.x + h4.y*wr4.y + h4.z*wr4.z + h4.w*wr4.w;
                    accU[i] += h4.x*wu4.x + h4.y*wu4.y + h4.z*wu4.z + h4.w*wu4.w;
                }
            }
            __syncthreads();
        }
#pragma unroll
        for (int i = 0; i < 4; ++i) {
            int b = bg + i * 16;
            size_t base = ((size_t)b * SS + t) * HH + j;
            float dr = g_Dr[base], dw = g_Dw[base], gg = g_G[b*SS + t];
            float hold = __ldcg(hcur + b*HH + j);
            float r  = 1.f / (1.f + expf(-(dr + accR[i] + burj)));
            float ht = tanhf(dw + r * (accU[i] + buj));
            float hnew = gg * ht + (1.f - gg) * hold;
            hnxt[b*HH + j] = hnew;
            hs_out[base] = hnew;
        }
        grid_sync((unsigned)(t + 1));
    }
}

// ---- next_mem ----
__global__ void next_mem_kernel(const float* __restrict__ P, const float* __restrict__ Q,
                                const float* __restrict__ Wm, const float* __restrict__ bm,
                                float* __restrict__ out) {
    __shared__ float srow[H3];
    int b = blockIdx.x, tid = threadIdx.x;
    for (int i = tid; i < HH; i += 256) {
        srow[i]        = P[b*HH + i];
        srow[HH + i]   = g_hping[b*HH + i];
        srow[2*HH + i] = Q[b*HH + i];
    }
    __syncthreads();
    float a0 = bm[tid], a1 = bm[tid+256], a2 = bm[tid+512], a3 = bm[tid+768];
    for (int k = 0; k < H3; ++k) {
        float s = srow[k];
        const float* w = Wm + (size_t)k*HH + tid;
        a0 += s*w[0]; a1 += s*w[256]; a2 += s*w[512]; a3 += s*w[768];
    }
    out[b*HH+tid]     = fmaxf(a0, 0.f);
    out[b*HH+tid+256] = fmaxf(a1, 0.f);
    out[b*HH+tid+512] = fmaxf(a2, 0.f);
    out[b*HH+tid+768] = fmaxf(a3, 0.f);
}

extern "C" void kernel_launch(void* const* d_in, const int* in_sizes, int n_in,
                              void* d_out, int out_size) {
    const float* D   = (const float*)d_in[0];
    const float* Q   = (const float*)d_in[1];
    const float* P   = (const float*)d_in[2];
    const float* Wr  = (const float*)d_in[3];
    const float* br  = (const float*)d_in[4];
    const float* Ur  = (const float*)d_in[5];
    const float* bur = (const float*)d_in[6];
    const float* Wx  = (const float*)d_in[7];
    const float* bx  = (const float*)d_in[8];
    const float* U   = (const float*)d_in[9];
    const float* bu  = (const float*)d_in[10];
    const float* W1  = (const float*)d_in[11];
    const float* b1  = (const float*)d_in[12];
    const float* W2  = (const float*)d_in[13];
    const float* b2  = (const float*)d_in[14];
    const float* Wm  = (const float*)d_in[15];
    const float* bm  = (const float*)d_in[16];

    float* out_next = (float*)d_out;
    float* out_hs   = (float*)d_out + BB * HH;

    static int attr_set = 0;
    if (!attr_set) {
        cudaFuncSetAttribute(scan_kernel, cudaFuncAttributeMaxDynamicSharedMemorySize, SCAN_SMEM);
        cudaFuncSetAttribute(gemm_hmma, cudaFuncAttributeMaxDynamicSharedMemorySize, G_SMEM_BYTES);
        attr_set = 1;
    }

    __nv_bfloat16 *zh, *zl, *dh, *dl, *w1th, *w1tl, *wrth, *wrtl, *wxth, *wxtl;
    float *gh1, *gDr, *gDw, *gUrT, *gUT;
    cudaGetSymbolAddress((void**)&zh, g_zh);
    cudaGetSymbolAddress((void**)&zl, g_zl);
    cudaGetSymbolAddress((void**)&dh, g_dh);
    cudaGetSymbolAddress((void**)&dl, g_dl);
    cudaGetSymbolAddress((void**)&w1th, g_w1th);
    cudaGetSymbolAddress((void**)&w1tl, g_w1tl);
    cudaGetSymbolAddress((void**)&wrth, g_wrth);
    cudaGetSymbolAddress((void**)&wrtl, g_wrtl);
    cudaGetSymbolAddress((void**)&wxth, g_wxth);
    cudaGetSymbolAddress((void**)&wxtl, g_wxtl);
    cudaGetSymbolAddress((void**)&gh1, g_h1);
    cudaGetSymbolAddress((void**)&gDr, g_Dr);
    cudaGetSymbolAddress((void**)&gDw, g_Dw);
    cudaGetSymbolAddress((void**)&gUrT, g_UrT);
    cudaGetSymbolAddress((void**)&gUT, g_UT);

    // launch index:            0
    build_feats<<<MM*(HH/4)/256, 256>>>(D, Q, P);
    //                          1..3
    wtsplit_kernel<<<dim3(HH/32, H4/32), dim3(32, 8)>>>(W1, w1th, w1tl, H4, HH);
    wtsplit_kernel<<<dim3(HH/32, HH/32), dim3(32, 8)>>>(Wr, wrth, wrtl, HH, HH);
    wtsplit_kernel<<<dim3(HH/32, HH/32), dim3(32, 8)>>>(Wx, wxth, wxtl, HH, HH);
    //                          4  <-- ncu -s 5 profiles this launch
    gemm_hmma<<<dim3(HH/128, MM/128), 256, G_SMEM_BYTES>>>(zh, zl, w1th, w1tl, b1, gh1, MM, HH, H4, 1);
    zs_gemv_kernel<<<MM, 128>>>(W2, b2);
    softmax_kernel<<<BB, 256>>>();
    gemm_hmma<<<dim3(HH/128, MM/128), 256, G_SMEM_BYTES>>>(dh, dl, wrth, wrtl, br, gDr, MM, HH, HH, 0);
    gemm_hmma<<<dim3(HH/128, MM/128), 256, G_SMEM_BYTES>>>(dh, dl, wxth, wxtl, bx, gDw, MM, HH, HH, 0);
    transpose_kernel<<<dim3(32, 32), dim3(32, 8)>>>(Ur, gUrT);
    transpose_kernel<<<dim3(32, 32), dim3(32, 8)>>>(U, gUT);
    init_kernel<<<256, 256>>>();
    scan_kernel<<<NCTA_SCAN, 128, SCAN_SMEM>>>(bur, bu, out_hs);
    next_mem_kernel<<<BB, 256>>>(P, Q, Wm, bm, out_next);
}

// round 6
// speedup vs baseline: 1.7821x; 1.0066x over previous
#include <cuda_runtime.h>
#include <cuda_bf16.h>
#include <cstdint>
#include <math.h>

#define BB 64
#define SS 256
#define HH 1024
#define MM (BB*SS)
#define H4 (4*HH)
#define H3 (3*HH)
#define NCTA_SCAN 128
#define TS 40   // gemm smem tile stride (bf16), pad 8

__device__ __nv_bfloat16 g_zh[(size_t)MM * H4];
__device__ __nv_bfloat16 g_zl[(size_t)MM * H4];
__device__ __nv_bfloat16 g_dh[(size_t)MM * HH];
__device__ __nv_bfloat16 g_dl[(size_t)MM * HH];
__device__ __nv_bfloat16 g_w1th[(size_t)HH * H4];
__device__ __nv_bfloat16 g_w1tl[(size_t)HH * H4];
__device__ __nv_bfloat16 g_wrth[HH * HH];
__device__ __nv_bfloat16 g_wrtl[HH * HH];
__device__ __nv_bfloat16 g_wxth[HH * HH];
__device__ __nv_bfloat16 g_wxtl[HH * HH];
__device__ float g_h1[(size_t)MM * HH];
__device__ float g_Dr[(size_t)MM * HH];
__device__ float g_Dw[(size_t)MM * HH];
__device__ float g_Zs[MM];
__device__ float g_G[MM];
__device__ float g_UrT[HH * HH];
__device__ float g_UT[HH * HH];
__device__ float g_hping[BB * HH];
__device__ float g_hpong[BB * HH];
__device__ unsigned g_bar_count;
__device__ unsigned g_bar_gen;

// ---- helpers ----
__device__ __forceinline__ uint32_t smem_u32(const void* p) {
    uint32_t a;
    asm("{ .reg .u64 t; cvta.to.shared.u64 t, %1; cvt.u32.u64 %0, t; }" : "=r"(a) : "l"(p));
    return a;
}
__device__ __forceinline__ void cpasync16(uint32_t s, const void* g) {
    asm volatile("cp.async.cg.shared.global [%0], [%1], 16;" :: "r"(s), "l"(g));
}
#define CP_COMMIT() asm volatile("cp.async.commit_group;" ::: "memory")
#define CP_WAIT1()  asm volatile("cp.async.wait_group 1;" ::: "memory")
#define LDSM4(r0,r1,r2,r3,addr) \
    asm volatile("ldmatrix.sync.aligned.m8n8.x4.shared.b16 {%0,%1,%2,%3}, [%4];" \
        : "=r"(r0), "=r"(r1), "=r"(r2), "=r"(r3) : "r"(addr))

__device__ __forceinline__ void mma16816(float* c, const uint32_t* a, uint32_t b0, uint32_t b1) {
    asm volatile("mma.sync.aligned.m16n8k16.row.col.f32.bf16.bf16.f32 "
        "{%0,%1,%2,%3}, {%4,%5,%6,%7}, {%8,%9}, {%0,%1,%2,%3};"
        : "+f"(c[0]), "+f"(c[1]), "+f"(c[2]), "+f"(c[3])
        : "r"(a[0]), "r"(a[1]), "r"(a[2]), "r"(a[3]), "r"(b0), "r"(b1));
}

__device__ __forceinline__ void split_store4(float4 v, __nv_bfloat16* hp, __nv_bfloat16* lp) {
    __nv_bfloat16 h0=__float2bfloat16_rn(v.x), h1=__float2bfloat16_rn(v.y),
                  h2=__float2bfloat16_rn(v.z), h3=__float2bfloat16_rn(v.w);
    __nv_bfloat16 l0=__float2bfloat16_rn(v.x-__bfloat162float(h0)),
                  l1=__float2bfloat16_rn(v.y-__bfloat162float(h1)),
                  l2=__float2bfloat16_rn(v.z-__bfloat162float(h2)),
                  l3=__float2bfloat16_rn(v.w-__bfloat162float(h3));
    *(ushort4*)hp = make_ushort4(__bfloat16_as_ushort(h0),__bfloat16_as_ushort(h1),
                                 __bfloat16_as_ushort(h2),__bfloat16_as_ushort(h3));
    *(ushort4*)lp = make_ushort4(__bfloat16_as_ushort(l0),__bfloat16_as_ushort(l1),
                                 __bfloat16_as_ushort(l2),__bfloat16_as_ushort(l3));
}

// ---- z features hi/lo + D hi/lo (merged) ----
__global__ void build_feats(const float* __restrict__ D, const float* __restrict__ Q,
                            const float* __restrict__ P) {
    int idx = blockIdx.x * blockDim.x + threadIdx.x;
    if (idx >= MM * (HH/4)) return;
    int k4 = idx & 255, m = idx >> 8, b = m >> 8;
    float4 d = ((const float4*)D)[idx];
    float4 q = ((const float4*)Q)[(b << 8) + k4];
    float4 p = ((const float4*)P)[(b << 8) + k4];
    __nv_bfloat16* zh = g_zh + (size_t)m * H4;
    __nv_bfloat16* zl = g_zl + (size_t)m * H4;
    int c = k4 * 4;
    split_store4(make_float4(d.x*q.x,d.y*q.y,d.z*q.z,d.w*q.w), zh+c, zl+c);
    split_store4(make_float4(d.x*p.x,d.y*p.y,d.z*p.z,d.w*p.w), zh+HH+c, zl+HH+c);
    split_store4(make_float4(fabsf(d.x-q.x),fabsf(d.y-q.y),fabsf(d.z-q.z),fabsf(d.w-q.w)), zh+2*HH+c, zl+2*HH+c);
    split_store4(make_float4(fabsf(d.x-p.x),fabsf(d.y-p.y),fabsf(d.z-p.z),fabsf(d.w-p.w)), zh+3*HH+c, zl+3*HH+c);
    split_store4(d, g_dh + (size_t)idx*4, g_dl + (size_t)idx*4);
}

// W[K][N] -> WT hi/lo [N][K]
__global__ void wtsplit_kernel(const float* __restrict__ W, __nv_bfloat16* __restrict__ Th,
                               __nv_bfloat16* __restrict__ Tl, int K, int N) {
    __shared__ float tile[32][33];
    int x = blockIdx.x*32 + threadIdx.x, y = blockIdx.y*32 + threadIdx.y;
#pragma unroll
    for (int i = 0; i < 4; ++i)
        tile[threadIdx.y + i*8][threadIdx.x] = W[(size_t)(y + i*8)*N + x];
    __syncthreads();
    int n = blockIdx.x*32 + threadIdx.y, k = blockIdx.y*32 + threadIdx.x;
#pragma unroll
    for (int i = 0; i < 4; ++i) {
        float v = tile[threadIdx.x][threadIdx.y + i*8];
        __nv_bfloat16 h = __float2bfloat16_rn(v);
        size_t o = (size_t)(n + i*8)*K + k;
        Th[o] = h;
        Tl[o] = __float2bfloat16_rn(v - __bfloat162float(h));
    }
}

__global__ void transpose_kernel(const float* __restrict__ src, float* __restrict__ dst) {
    __shared__ float tile[32][33];
    int x = blockIdx.x*32 + threadIdx.x, y = blockIdx.y*32 + threadIdx.y;
#pragma unroll
    for (int i = 0; i < 4; ++i)
        tile[threadIdx.y + i*8][threadIdx.x] = src[(size_t)(y + i*8)*HH + x];
    __syncthreads();
    x = blockIdx.y*32 + threadIdx.x; y = blockIdx.x*32 + threadIdx.y;
#pragma unroll
    for (int i = 0; i < 4; ++i)
        dst[(size_t)(y + i*8)*HH + x] = tile[threadIdx.x][threadIdx.y + i*8];
}

// ---- HMMA split-bf16 GEMM with ldmatrix fragments ----
#define G_SMEM_BYTES (2 * 4 * 128 * TS * 2)
__global__ __launch_bounds__(256, 2) void gemm_hmma(
        const __nv_bfloat16* __restrict__ Ah, const __nv_bfloat16* __restrict__ Al,
        const __nv_bfloat16* __restrict__ Bh, const __nv_bfloat16* __restrict__ Bl,
        const float* __restrict__ bias, float* __restrict__ C,
        int M, int N, int K, int act) {
    extern __shared__ __nv_bfloat16 sm[];
    const int tid = threadIdx.x, wid = tid >> 5, lane = tid & 31;
    const int wm = wid >> 1, wn = wid & 1;
    const int g = lane >> 2, t = lane & 3;
    const int bm = blockIdx.y * 128, bn = blockIdx.x * 128;
    const int BUF = 4 * 128 * TS;           // bf16 elems per buffer

    float acc[2][8][4];
#pragma unroll
    for (int i = 0; i < 2; ++i)
#pragma unroll
        for (int j = 0; j < 8; ++j)
#pragma unroll
            for (int q = 0; q < 4; ++q) acc[i][j][q] = 0.f;

    const int rA = tid >> 2, sA = tid & 3;
    const int rB = (tid + 256) >> 2, sB = (tid + 256) & 3;
    const int nch = K >> 5;
    const uint32_t smb = smem_u32(sm);

    // ldmatrix per-lane offsets (bytes)
    const uint32_t aoff = (uint32_t)(((lane & 15) * TS + ((lane >> 4) << 3)) * 2);
    const uint32_t boff = (uint32_t)(((((lane >> 4) & 1) * 8 + (lane & 7)) * TS
                                     + (((lane >> 3) & 1) << 3)) * 2);

    {   // prefetch chunk 0
#pragma unroll
        for (int p = 0; p < 2; ++p) {
            int r = p ? rB : rA, s = p ? sB : sA;
            uint32_t so = (uint32_t)((r*TS + s*8) * 2);
            size_t ga = (size_t)(bm + r)*K + s*8;
            size_t gb = (size_t)(bn + r)*K + s*8;
            cpasync16(smb + so,              Ah + ga);
            cpasync16(smb + 128*TS*2 + so,   Al + ga);
            cpasync16(smb + 2*128*TS*2 + so, Bh + gb);
            cpasync16(smb + 3*128*TS*2 + so, Bl + gb);
        }
    }
    CP_COMMIT();

    for (int c = 0; c < nch; ++c) {
        if (c + 1 < nch) {
            const size_t k0 = (size_t)(c + 1) * 32;
            uint32_t bufo = (uint32_t)(((c + 1) & 1) * BUF * 2);
#pragma unroll
            for (int p = 0; p < 2; ++p) {
                int r = p ? rB : rA, s = p ? sB : sA;
                uint32_t so = bufo + (uint32_t)((r*TS + s*8) * 2);
                size_t ga = (size_t)(bm + r)*K + k0 + s*8;
                size_t gb = (size_t)(bn + r)*K + k0 + s*8;
                cpasync16(smb + so,              Ah + ga);
                cpasync16(smb + 128*TS*2 + so,   Al + ga);
                cpasync16(smb + 2*128*TS*2 + so, Bh + gb);
                cpasync16(smb + 3*128*TS*2 + so, Bl + gb);
            }
        }
        CP_COMMIT();
        CP_WAIT1();
        __syncthreads();

        const uint32_t bb  = smb + (uint32_t)((c & 1) * BUF * 2);
        const uint32_t aAh = bb;
        const uint32_t aAl = bb + 128*TS*2;
        const uint32_t aBh = bb + 2*128*TS*2;
        const uint32_t aBl = bb + 3*128*TS*2;

#pragma unroll
        for (int kk = 0; kk < 32; kk += 16) {
            uint32_t ah[2][4], al[2][4];
#pragma unroll
            for (int i = 0; i < 2; ++i) {
                uint32_t ro = (uint32_t)(((wm*32 + i*16)*TS + kk) * 2);
                LDSM4(ah[i][0], ah[i][1], ah[i][2], ah[i][3], aAh + ro + aoff);
                LDSM4(al[i][0], al[i][1], al[i][2], al[i][3], aAl + ro + aoff);
            }
#pragma unroll
            for (int jj = 0; jj < 4; ++jj) {
                uint32_t co = (uint32_t)(((wn*64 + jj*16)*TS + kk) * 2);
                uint32_t bh0, bh1, bh2, bh3, bl0, bl1, bl2, bl3;
                LDSM4(bh0, bh1, bh2, bh3, aBh + co + boff);
                LDSM4(bl0, bl1, bl2, bl3, aBl + co + boff);
#pragma unroll
                for (int i = 0; i < 2; ++i) {
                    mma16816(acc[i][2*jj],   ah[i], bh0, bh1);
                    mma16816(acc[i][2*jj],   ah[i], bl0, bl1);
                    mma16816(acc[i][2*jj],   al[i], bh0, bh1);
                    mma16816(acc[i][2*jj+1], ah[i], bh2, bh3);
                    mma16816(acc[i][2*jj+1], ah[i], bl2, bl3);
                    mma16816(acc[i][2*jj+1], al[i], bh2, bh3);
                }
            }
        }
        __syncthreads();
    }

#pragma unroll
    for (int i = 0; i < 2; ++i) {
#pragma unroll
        for (int j = 0; j < 8; ++j) {
            int row = bm + wm*32 + i*16 + g;
            int col = bn + wn*64 + j*8 + 2*t;
            float b0 = bias[col], b1 = bias[col+1];
            float v0 = acc[i][j][0] + b0, v1 = acc[i][j][1] + b1;
            float v2 = acc[i][j][2] + b0, v3 = acc[i][j][3] + b1;
            if (act) { v0=tanhf(v0); v1=tanhf(v1); v2=tanhf(v2); v3=tanhf(v3); }
            *(float2*)(C + (size_t)row*N + col)     = make_float2(v0, v1);
            *(float2*)(C + (size_t)(row+8)*N + col) = make_float2(v2, v3);
        }
    }
}

// ---- Zs GEMV + softmax ----
__global__ void zs_gemv_kernel(const float* __restrict__ W2, const float* __restrict__ b2) {
    int m = blockIdx.x, tid = threadIdx.x;
    const float4* hr = (const float4*)(g_h1 + (size_t)m * HH);
    const float4* w = (const float4*)W2;
    float s = 0.f;
#pragma unroll
    for (int k = tid; k < 256; k += 128) {
        float4 a = hr[k], bb = w[k];
        s += a.x*bb.x + a.y*bb.y + a.z*bb.z + a.w*bb.w;
    }
#pragma unroll
    for (int off = 16; off; off >>= 1) s += __shfl_down_sync(0xffffffffu, s, off);
    __shared__ float ws[4];
    if ((tid & 31) == 0) ws[tid >> 5] = s;
    __syncthreads();
    if (tid == 0) g_Zs[m] = ws[0] + ws[1] + ws[2] + ws[3] + b2[0];
}

__global__ void softmax_kernel() {
    int b = blockIdx.x, tid = threadIdx.x;
    __shared__ float red[256];
    float v = g_Zs[b * SS + tid];
    red[tid] = v; __syncthreads();
#pragma unroll
    for (int off = 128; off; off >>= 1) {
        if (tid < off) red[tid] = fmaxf(red[tid], red[tid + off]);
        __syncthreads();
    }
    float mx = red[0]; __syncthreads();
    float e = expf(v - mx);
    red[tid] = e; __syncthreads();
#pragma unroll
    for (int off = 128; off; off >>= 1) {
        if (tid < off) red[tid] += red[tid + off];
        __syncthreads();
    }
    g_G[b * SS + tid] = e / red[0];
}

__global__ void init_kernel() {
    int i = blockIdx.x * blockDim.x + threadIdx.x;
    if (i < BB * HH) g_hping[i] = 0.f;
    if (i == 0) { g_bar_count = 0u; g_bar_gen = 0u; }
}

__device__ __forceinline__ void grid_sync(unsigned target) {
    __syncthreads();
    if (threadIdx.x == 0) {
        __threadfence();
        unsigned prev = atomicAdd(&g_bar_count, 1u);
        if (prev == NCTA_SCAN - 1) {
            g_bar_count = 0u;
            __threadfence();
            atomicExch(&g_bar_gen, target);
        } else {
            while (*((volatile unsigned*)&g_bar_gen) < target) { __nanosleep(32); }
        }
        __threadfence();
    }
    __syncthreads();
}

// ---- persistent scan: cp.async double-buffered h-chunks ----
#define SCAN_SMEM ((16*1028 + 2*64*68) * 4)
__global__ __launch_bounds__(128) void scan_kernel(const float* __restrict__ bur,
                                                   const float* __restrict__ bu,
                                                   float* __restrict__ hs_out) {
    extern __shared__ float smf[];
    float* wr_s = smf;
    float* wu_s = smf + 8 * 1028;
    float* sh   = smf + 16 * 1028;   // [2][64][68]
    const int tid = threadIdx.x;
    const int jl = tid & 7, bg = tid >> 3;
    const int j = blockIdx.x * 8 + jl;

    for (int idx = tid; idx < 2048; idx += 128) {
        int jj = idx >> 8, k4 = idx & 255;
        *(float4*)&wr_s[jj*1028 + k4*4] = *(const float4*)(g_UrT + (size_t)(blockIdx.x*8+jj)*HH + k4*4);
        *(float4*)&wu_s[jj*1028 + k4*4] = *(const float4*)(g_UT  + (size_t)(blockIdx.x*8+jj)*HH + k4*4);
    }
    const float burj = bur[j], buj = bu[j];
    __syncthreads();

    const int r0 = tid >> 4, c4 = (tid & 15) * 4;
    const uint32_t shb = smem_u32(sh);

    for (int t = 0; t < SS; ++t) {
        const float* hcur = (t & 1) ? g_hpong : g_hping;
        float*       hnxt = (t & 1) ? g_hping : g_hpong;
        float accR[4] = {0,0,0,0}, accU[4] = {0,0,0,0};

#pragma unroll
        for (int r = 0; r < 8; ++r)
            cpasync16(shb + ((r0 + r*8)*68 + c4)*4,
                      hcur + (size_t)(r0 + r*8)*HH + c4);
        CP_COMMIT();

        for (int c = 0; c < 16; ++c) {
            if (c + 1 < 16) {
                int kcn = (c + 1) * 64;
                uint32_t bo = (uint32_t)(((c + 1) & 1) * 64 * 68 * 4);
#pragma unroll
                for (int r = 0; r < 8; ++r)
                    cpasync16(shb + bo + ((r0 + r*8)*68 + c4)*4,
                              hcur + (size_t)(r0 + r*8)*HH + kcn + c4);
            }
            CP_COMMIT();
            CP_WAIT1();
            __syncthreads();

            const float* shc = sh + (c & 1) * 64 * 68;
            const int kc = c * 64;
#pragma unroll
            for (int k = 0; k < 64; k += 4) {
                float4 wr4 = *(const float4*)&wr_s[jl*1028 + kc + k];
                float4 wu4 = *(const float4*)&wu_s[jl*1028 + kc + k];
#pragma unroll
                for (int i = 0; i < 4; ++i) {
                    float4 h4 = *(const float4*)&shc[(bg + i*16)*68 + k];
                    accR[i] += h4.x*wr4.x + h4.y*wr4.y + h4.z*wr4.z + h4.w*wr4.w;
                    accU[i] += h4.x*wu4.x + h4.y*wu4.y + h4.z*wu4.z + h4.w*wu4.w;
                }
            }
            __syncthreads();
        }
#pragma unroll
        for (int i = 0; i < 4; ++i) {
            int b = bg + i * 16;
            size_t base = ((size_t)b * SS + t) * HH + j;
            float dr = g_Dr[base], dw = g_Dw[base], gg = g_G[b*SS + t];
            float hold = __ldcg(hcur + b*HH + j);
            float r  = 1.f / (1.f + expf(-(dr + accR[i] + burj)));
            float ht = tanhf(dw + r * (accU[i] + buj));
            float hnew = gg * ht + (1.f - gg) * hold;
            hnxt[b*HH + j] = hnew;
            hs_out[base] = hnew;
        }
        grid_sync((unsigned)(t + 1));
    }
}

// ---- next_mem ----
__global__ void next_mem_kernel(const float* __restrict__ P, const float* __restrict__ Q,
                                const float* __restrict__ Wm, const float* __restrict__ bm,
                                float* __restrict__ out) {
    __shared__ float srow[H3];
    int b = blockIdx.x, tid = threadIdx.x;
    for (int i = tid; i < HH; i += 256) {
        srow[i]        = P[b*HH + i];
        srow[HH + i]   = g_hping[b*HH + i];
        srow[2*HH + i] = Q[b*HH + i];
    }
    __syncthreads();
    float a0 = bm[tid], a1 = bm[tid+256], a2 = bm[tid+512], a3 = bm[tid+768];
    for (int k = 0; k < H3; ++k) {
        float s = srow[k];
        const float* w = Wm + (size_t)k*HH + tid;
        a0 += s*w[0]; a1 += s*w[256]; a2 += s*w[512]; a3 += s*w[768];
    }
    out[b*HH+tid]     = fmaxf(a0, 0.f);
    out[b*HH+tid+256] = fmaxf(a1, 0.f);
    out[b*HH+tid+512] = fmaxf(a2, 0.f);
    out[b*HH+tid+768] = fmaxf(a3, 0.f);
}

extern "C" void kernel_launch(void* const* d_in, const int* in_sizes, int n_in,
                              void* d_out, int out_size) {
    const float* D   = (const float*)d_in[0];
    const float* Q   = (const float*)d_in[1];
    const float* P   = (const float*)d_in[2];
    const float* Wr  = (const float*)d_in[3];
    const float* br  = (const float*)d_in[4];
    const float* Ur  = (const float*)d_in[5];
    const float* bur = (const float*)d_in[6];
    const float* Wx  = (const float*)d_in[7];
    const float* bx  = (const float*)d_in[8];
    const float* U   = (const float*)d_in[9];
    const float* bu  = (const float*)d_in[10];
    const float* W1  = (const float*)d_in[11];
    const float* b1  = (const float*)d_in[12];
    const float* W2  = (const float*)d_in[13];
    const float* b2  = (const float*)d_in[14];
    const float* Wm  = (const float*)d_in[15];
    const float* bm  = (const float*)d_in[16];

    float* out_next = (float*)d_out;
    float* out_hs   = (float*)d_out + BB * HH;

    static int attr_set = 0;
    if (!attr_set) {
        cudaFuncSetAttribute(scan_kernel, cudaFuncAttributeMaxDynamicSharedMemorySize, SCAN_SMEM);
        cudaFuncSetAttribute(gemm_hmma, cudaFuncAttributeMaxDynamicSharedMemorySize, G_SMEM_BYTES);
        attr_set = 1;
    }

    __nv_bfloat16 *zh, *zl, *dh, *dl, *w1th, *w1tl, *wrth, *wrtl, *wxth, *wxtl;
    float *gh1, *gDr, *gDw, *gUrT, *gUT;
    cudaGetSymbolAddress((void**)&zh, g_zh);
    cudaGetSymbolAddress((void**)&zl, g_zl);
    cudaGetSymbolAddress((void**)&dh, g_dh);
    cudaGetSymbolAddress((void**)&dl, g_dl);
    cudaGetSymbolAddress((void**)&w1th, g_w1th);
    cudaGetSymbolAddress((void**)&w1tl, g_w1tl);
    cudaGetSymbolAddress((void**)&wrth, g_wrth);
    cudaGetSymbolAddress((void**)&wrtl, g_wrtl);
    cudaGetSymbolAddress((void**)&wxth, g_wxth);
    cudaGetSymbolAddress((void**)&wxtl, g_wxtl);
    cudaGetSymbolAddress((void**)&gh1, g_h1);
    cudaGetSymbolAddress((void**)&gDr, g_Dr);
    cudaGetSymbolAddress((void**)&gDw, g_Dw);
    cudaGetSymbolAddress((void**)&gUrT, g_UrT);
    cudaGetSymbolAddress((void**)&gUT, g_UT);

    // idx 0
    build_feats<<<MM*(HH/4)/256, 256>>>(D, Q, P);
    // idx 1, 2
    wtsplit_kernel<<<dim3(HH/32, H4/32), dim3(32, 8)>>>(W1, w1th, w1tl, H4, HH);
    wtsplit_kernel<<<dim3(HH/32, HH/32), dim3(32, 8)>>>(Wr, wrth, wrtl, HH, HH);
    // idx 3  <-- ncu window should land here
    gemm_hmma<<<dim3(HH/128, MM/128), 256, G_SMEM_BYTES>>>(zh, zl, w1th, w1tl, b1, gh1, MM, HH, H4, 1);
    // rest
    wtsplit_kernel<<<dim3(HH/32, HH/32), dim3(32, 8)>>>(Wx, wxth, wxtl, HH, HH);
    zs_gemv_kernel<<<MM, 128>>>(W2, b2);
    softmax_kernel<<<BB, 256>>>();
    gemm_hmma<<<dim3(HH/128, MM/128), 256, G_SMEM_BYTES>>>(dh, dl, wrth, wrtl, br, gDr, MM, HH, HH, 0);
    gemm_hmma<<<dim3(HH/128, MM/128), 256, G_SMEM_BYTES>>>(dh, dl, wxth, wxtl, bx, gDw, MM, HH, HH, 0);
    transpose_kernel<<<dim3(32, 32), dim3(32, 8)>>>(Ur, gUrT);
    transpose_kernel<<<dim3(32, 32), dim3(32, 8)>>>(U, gUT);
    init_kernel<<<256, 256>>>();
    scan_kernel<<<NCTA_SCAN, 128, SCAN_SMEM>>>(bur, bu, out_hs);
    next_mem_kernel<<<BB, 256>>>(P, Q, Wm, bm, out_next);
}